// round 10
// baseline (speedup 1.0000x reference)
#include <cuda_runtime.h>
#include <cuda_fp16.h>
#include <cstdint>

#define BSZ  4
#define CCH  256
#define NTOK 4096

#define BM   128
#define BN   32
#define ITERS (NTOK / BN)

// ---------------- static device scratch (no allocation allowed) ----------------
__device__ __half g_th_hi[(size_t)BSZ * NTOK * CCH];
__device__ __half g_th_lo[(size_t)BSZ * NTOK * CCH];
__device__ __half g_ph_hi[(size_t)BSZ * NTOK * CCH];
__device__ __half g_ph_lo[(size_t)BSZ * NTOK * CCH];
__device__ __half g_gv  [(size_t)BSZ * NTOK * CCH];
__device__ __half g_y_hi[(size_t)BSZ * NTOK * CCH];
__device__ __half g_y_lo[(size_t)BSZ * NTOK * CCH];
__device__ __half g_x_hi[(size_t)BSZ * CCH * NTOK];
__device__ __half g_x_lo[(size_t)BSZ * CCH * NTOK];
__device__ __half g_w_hi[4 * CCH * CCH];
__device__ __half g_w_lo[4 * CCH * CCH];

// ---------------- PTX helpers ----------------
__device__ __forceinline__ uint32_t smem_u32(const void* p) {
    return (uint32_t)__cvta_generic_to_shared(p);
}
__device__ __forceinline__ void cp16(uint32_t s, const void* g) {
    asm volatile("cp.async.cg.shared.global [%0], [%1], 16;\n" :: "r"(s), "l"(g));
}
#define CP_COMMIT() asm volatile("cp.async.commit_group;\n" ::: "memory")
#define CP_WAIT(n)  asm volatile("cp.async.wait_group %0;\n" :: "n"(n) : "memory")

__device__ __forceinline__ void ldsm4(uint32_t& r0, uint32_t& r1, uint32_t& r2, uint32_t& r3,
                                      uint32_t a) {
    asm volatile("ldmatrix.sync.aligned.m8n8.x4.shared.b16 {%0,%1,%2,%3}, [%4];\n"
                 : "=r"(r0), "=r"(r1), "=r"(r2), "=r"(r3) : "r"(a));
}
__device__ __forceinline__ void ldsm4t(uint32_t& r0, uint32_t& r1, uint32_t& r2, uint32_t& r3,
                                       uint32_t a) {
    asm volatile("ldmatrix.sync.aligned.m8n8.x4.trans.shared.b16 {%0,%1,%2,%3}, [%4];\n"
                 : "=r"(r0), "=r"(r1), "=r"(r2), "=r"(r3) : "r"(a));
}
__device__ __forceinline__ void mma16816(float* c, uint32_t a0, uint32_t a1, uint32_t a2,
                                         uint32_t a3, uint32_t b0, uint32_t b1) {
    asm volatile("mma.sync.aligned.m16n8k16.row.col.f32.f16.f16.f32 "
                 "{%0,%1,%2,%3}, {%4,%5,%6,%7}, {%8,%9}, {%0,%1,%2,%3};\n"
                 : "+f"(c[0]), "+f"(c[1]), "+f"(c[2]), "+f"(c[3])
                 : "r"(a0), "r"(a1), "r"(a2), "r"(a3), "r"(b0), "r"(b1));
}
__device__ __forceinline__ uint32_t h2pack(float a, float b) {
    __half2 h = __floats2half2_rn(a, b);
    return *reinterpret_cast<uint32_t*>(&h);
}

// ---- swizzled tile loaders: row stride 512B, 16B chunk c stored at (c ^ (row&7))
__device__ __forceinline__ void load_tile32_sw(char* dst, const __half* src, int t) {
    #pragma unroll
    for (int i = 0; i < 4; i++) {
        int idx = t + (i << 8);
        int r = idx >> 5, c = idx & 31;
        cp16(smem_u32(dst + r * 512 + ((c ^ (r & 7)) << 4)), src + (r << 8) + (c << 3));
    }
}
__device__ __forceinline__ void load_tile128_sw(char* dst, const __half* src, int t) {
    #pragma unroll
    for (int i = 0; i < 16; i++) {
        int idx = t + (i << 8);
        int r = idx >> 5, c = idx & 31;
        cp16(smem_u32(dst + r * 512 + ((c ^ (r & 7)) << 4)), src + (r << 8) + (c << 3));
    }
}

extern __shared__ char smem_raw[];

// =============================================================================
// Prep: split fp32 -> (hi, lo) fp16 pairs. One launch: x part + w part.
// =============================================================================
__global__ void split_all_kernel(const float* __restrict__ x,
                                 const float* __restrict__ w0, const float* __restrict__ w1,
                                 const float* __restrict__ w2, const float* __restrict__ w3) {
    const int blk = blockIdx.x;
    const float* __restrict__ src;
    __half *dhi, *dlo;
    int i;
    if (blk < 4096) {
        i = (blk * 256 + threadIdx.x) * 4;
        src = x; dhi = g_x_hi; dlo = g_x_lo;
    } else {
        const int wsel = (blk - 4096) >> 6;
        const int wblk = (blk - 4096) & 63;
        i = (wblk * 256 + threadIdx.x) * 4;
        src = (wsel == 0) ? w0 : (wsel == 1) ? w1 : (wsel == 2) ? w2 : w3;
        dhi = g_w_hi + wsel * CCH * CCH; dlo = g_w_lo + wsel * CCH * CCH;
    }
    float4 v = *(const float4*)&src[i];
    __half h0 = __float2half(v.x), h1 = __float2half(v.y);
    __half h2 = __float2half(v.z), h3 = __float2half(v.w);
    *(__half2*)&dhi[i]     = __halves2half2(h0, h1);
    *(__half2*)&dhi[i + 2] = __halves2half2(h2, h3);
    *(__half2*)&dlo[i]     = __halves2half2(__float2half(v.x - __half2float(h0)),
                                            __float2half(v.y - __half2float(h1)));
    *(__half2*)&dlo[i + 2] = __halves2half2(__float2half(v.z - __half2float(h2)),
                                            __float2half(v.w - __half2float(h3)));
}

// =============================================================================
// proj_tc: out[oc,n] = sum_c w[oc,c] * x[c,n]   split-fp16, double-buffered k
// =============================================================================
#define PA_LD 40
#define PB_LD 136
#define PJ_STG 38912

__device__ __forceinline__ void proj_load_chunk(char* sb, const __half* Ah, const __half* Al,
                                                const __half* Bh, const __half* Bl,
                                                int m0, int n0, int k0, int t) {
    __half* sAh = (__half*)sb;
    __half* sAl = (__half*)(sb + 10240);
    __half* sBh = (__half*)(sb + 20480);
    __half* sBl = (__half*)(sb + 29184);
    {
        const int r = t >> 1, hoff = (t & 1) * 16;
        cp16(smem_u32(sAh + r * PA_LD + hoff),     Ah + (m0 + r) * CCH + k0 + hoff);
        cp16(smem_u32(sAh + r * PA_LD + hoff + 8), Ah + (m0 + r) * CCH + k0 + hoff + 8);
        cp16(smem_u32(sAl + r * PA_LD + hoff),     Al + (m0 + r) * CCH + k0 + hoff);
        cp16(smem_u32(sAl + r * PA_LD + hoff + 8), Al + (m0 + r) * CCH + k0 + hoff + 8);
    }
    {
        const int r = t >> 3, hoff = (t & 7) * 16;
        cp16(smem_u32(sBh + r * PB_LD + hoff),     Bh + (size_t)(k0 + r) * NTOK + n0 + hoff);
        cp16(smem_u32(sBh + r * PB_LD + hoff + 8), Bh + (size_t)(k0 + r) * NTOK + n0 + hoff + 8);
        cp16(smem_u32(sBl + r * PB_LD + hoff),     Bl + (size_t)(k0 + r) * NTOK + n0 + hoff);
        cp16(smem_u32(sBl + r * PB_LD + hoff + 8), Bl + (size_t)(k0 + r) * NTOK + n0 + hoff + 8);
    }
}

__global__ void __launch_bounds__(256) proj_tc_kernel() {
    const int b  = blockIdx.z / 3;
    const int w  = blockIdx.z % 3;
    const int n0 = blockIdx.x * 128;
    const int m0 = blockIdx.y * 128;

    const int t = threadIdx.x, lane = t & 31, warp = t >> 5;
    const int wr = warp & 3, wc = warp >> 2;

    const __half* __restrict__ Ah = g_w_hi + w * CCH * CCH;
    const __half* __restrict__ Al = g_w_lo + w * CCH * CCH;
    const __half* __restrict__ Bh = g_x_hi + (size_t)b * CCH * NTOK;
    const __half* __restrict__ Bl = g_x_lo + (size_t)b * CCH * NTOK;

    float acc[2][8][4] = {};
    const int gi = lane >> 3, li = lane & 7;
    const uint32_t aOff = (uint32_t)((wr * 32 + (lane & 15)) * PA_LD + ((lane >> 4) << 3)) * 2;
    const uint32_t bOff = (uint32_t)((((gi & 1) << 3) + li) * PB_LD + wc * 64 + ((gi >> 1) << 3)) * 2;

    proj_load_chunk(smem_raw, Ah, Al, Bh, Bl, m0, n0, 0, t);
    CP_COMMIT();

    for (int kc8 = 0; kc8 < 8; kc8++) {
        if (kc8 + 1 < 8) {
            proj_load_chunk(smem_raw + ((kc8 + 1) & 1) * PJ_STG, Ah, Al, Bh, Bl,
                            m0, n0, (kc8 + 1) * 32, t);
            CP_COMMIT();
            CP_WAIT(1);
        } else {
            CP_WAIT(0);
        }
        __syncthreads();

        char* sb = smem_raw + (kc8 & 1) * PJ_STG;
        const uint32_t sAh32 = smem_u32(sb);
        const uint32_t sAl32 = smem_u32(sb + 10240);
        const uint32_t sBh32 = smem_u32(sb + 20480);
        const uint32_t sBl32 = smem_u32(sb + 29184);

        #pragma unroll
        for (int ks = 0; ks < 2; ks++) {
            const uint32_t ka = ks * 32, kb = ks * 16 * PB_LD * 2;
            uint32_t ah[2][4], al[2][4];
            ldsm4(ah[0][0], ah[0][1], ah[0][2], ah[0][3], sAh32 + aOff + ka);
            ldsm4(ah[1][0], ah[1][1], ah[1][2], ah[1][3], sAh32 + aOff + ka + 16 * PA_LD * 2);
            ldsm4(al[0][0], al[0][1], al[0][2], al[0][3], sAl32 + aOff + ka);
            ldsm4(al[1][0], al[1][1], al[1][2], al[1][3], sAl32 + aOff + ka + 16 * PA_LD * 2);
            #pragma unroll
            for (int jn = 0; jn < 4; jn++) {
                uint32_t bhf[4], blf[4];
                ldsm4t(bhf[0], bhf[1], bhf[2], bhf[3], sBh32 + bOff + kb + jn * 32);
                ldsm4t(blf[0], blf[1], blf[2], blf[3], sBl32 + bOff + kb + jn * 32);
                #pragma unroll
                for (int mi = 0; mi < 2; mi++) {
                    mma16816(acc[mi][2 * jn + 0], ah[mi][0], ah[mi][1], ah[mi][2], ah[mi][3], bhf[0], bhf[1]);
                    mma16816(acc[mi][2 * jn + 1], ah[mi][0], ah[mi][1], ah[mi][2], ah[mi][3], bhf[2], bhf[3]);
                    mma16816(acc[mi][2 * jn + 0], ah[mi][0], ah[mi][1], ah[mi][2], ah[mi][3], blf[0], blf[1]);
                    mma16816(acc[mi][2 * jn + 1], ah[mi][0], ah[mi][1], ah[mi][2], ah[mi][3], blf[2], blf[3]);
                    mma16816(acc[mi][2 * jn + 0], al[mi][0], al[mi][1], al[mi][2], al[mi][3], bhf[0], bhf[1]);
                    mma16816(acc[mi][2 * jn + 1], al[mi][0], al[mi][1], al[mi][2], al[mi][3], bhf[2], bhf[3]);
                }
            }
        }
        __syncthreads();
    }

    __half* buf = (__half*)smem_raw;   // [128 n][136]
    const int mb = wr * 32 + (lane >> 2);
    const int nb = wc * 64 + (lane & 3) * 2;
    const int npass = (w == 2) ? 1 : 2;

    for (int pass = 0; pass < npass; pass++) {
        __syncthreads();
        #pragma unroll
        for (int mi = 0; mi < 2; mi++)
            #pragma unroll
            for (int jn = 0; jn < 8; jn++)
                #pragma unroll
                for (int e = 0; e < 4; e++) {
                    const float v = acc[mi][jn][e];
                    const int nl = nb + jn * 8 + (e & 1);
                    const int ml = mb + mi * 16 + ((e >> 1) << 3);
                    __half h = __float2half(v);
                    buf[nl * PB_LD + ml] = (pass == 0) ? h : __float2half(v - __half2float(h));
                }
        __syncthreads();
        __half* __restrict__ G;
        if (w == 0) G = (pass == 0) ? g_th_hi : g_th_lo;
        else if (w == 1) G = (pass == 0) ? g_ph_hi : g_ph_lo;
        else G = g_gv;
        G += (size_t)b * NTOK * CCH;
        #pragma unroll
        for (int i = 0; i < 8; i++) {
            const int fi = t * 8 + i;
            const int row = fi >> 4, col8 = (fi & 15) * 8;
            *(float4*)&G[(size_t)(n0 + row) * CCH + m0 + col8] = *(float4*)&buf[row * PB_LD + col8];
        }
    }
}

// =============================================================================
// flash attention: BM=128, BN=32, K/V double-buffered, ONE sync per iteration.
// smem 224K: Qh 0 | Ql 64K | K bufs 128K (stride 32K: hi 16K + lo 16K) | V bufs 192K (stride 16K)
// =============================================================================
__global__ void __launch_bounds__(256, 1) flash_kernel() {
    const int b  = blockIdx.y;
    const int n0 = blockIdx.x * BM;

    char* sQh = smem_raw;
    char* sQl = smem_raw + 65536;
    char* sKb = smem_raw + 131072;   // buf stride 32768 (Kh +0, Kl +16384)
    char* sVb = smem_raw + 196608;   // buf stride 16384

    const int t    = threadIdx.x;
    const int lane = t & 31;
    const int warp = t >> 5;
    const int wr0  = warp * 16;

    const __half* __restrict__ Qh = g_th_hi + ((size_t)b * NTOK + n0) * CCH;
    const __half* __restrict__ Ql = g_th_lo + ((size_t)b * NTOK + n0) * CCH;
    const __half* __restrict__ Kh = g_ph_hi + (size_t)b * NTOK * CCH;
    const __half* __restrict__ Kl = g_ph_lo + (size_t)b * NTOK * CCH;
    const __half* __restrict__ Vv = g_gv    + (size_t)b * NTOK * CCH;

    // prologue: Q + tile 0 (group 0)
    load_tile128_sw(sQh, Qh, t);
    load_tile128_sw(sQl, Ql, t);
    load_tile32_sw(sKb,         Kh, t);
    load_tile32_sw(sKb + 16384, Kl, t);
    load_tile32_sw(sVb,         Vv, t);
    CP_COMMIT();

    // ---- per-lane ldsm bases (swizzled: chunk' = chunk ^ (row & 7))
    const int gi = lane >> 3, li = lane & 7;
    const int arow = wr0 + (lane & 15);
    const uint32_t aSw = (uint32_t)(arow & 7);
    const uint32_t aS0 = (uint32_t)(lane >> 4);
    const uint32_t aHrb = smem_u32(sQh + arow * 512);
    const uint32_t aLrb = smem_u32(sQl + arow * 512);

    const int brow = ((gi >> 1) << 3) + li;
    const uint32_t bSw = (uint32_t)(brow & 7);
    const uint32_t bS  = (uint32_t)(gi & 1);
    const uint32_t bHrb0 = smem_u32(sKb + brow * 512);

    const int vrow = ((gi & 1) << 3) + li;
    const uint32_t vSw = (uint32_t)(vrow & 7);
    const uint32_t vS  = (uint32_t)(gi >> 1);
    const uint32_t vrb0 = smem_u32(sVb + vrow * 512);

    float o[32][4];
    #pragma unroll
    for (int nt = 0; nt < 32; nt++) { o[nt][0] = o[nt][1] = o[nt][2] = o[nt][3] = 0.0f; }
    float m0 = -1e30f, m1 = -1e30f, l0 = 0.0f, l1 = 0.0f;

    for (int it = 0; it < ITERS; it++) {
        CP_WAIT(0);           // tile it landed (issued 1 full iteration ago)
        __syncthreads();      // publish copies + retire buffer consumed last iter

        if (it + 1 < ITERS) { // prefetch tile it+1 into the freed buffer
            char* kb = sKb + ((it + 1) & 1) * 32768;
            char* vb = sVb + ((it + 1) & 1) * 16384;
            load_tile32_sw(kb,         Kh + (size_t)(it + 1) * BN * CCH, t);
            load_tile32_sw(kb + 16384, Kl + (size_t)(it + 1) * BN * CCH, t);
            load_tile32_sw(vb,         Vv + (size_t)(it + 1) * BN * CCH, t);
            CP_COMMIT();
        }

        const uint32_t bHrb = bHrb0 + (uint32_t)(it & 1) * 32768;
        const uint32_t bLrb = bHrb + 16384;
        const uint32_t vrb  = vrb0 + (uint32_t)(it & 1) * 16384;

        // ---- QK: S[16 x 32] per warp, split-fp16 (3 terms)
        float sc[4][4];
        #pragma unroll
        for (int j = 0; j < 4; j++) sc[j][0] = sc[j][1] = sc[j][2] = sc[j][3] = 0.0f;

        #pragma unroll 4
        for (int kc = 0; kc < 16; kc++) {
            const uint32_t offA = (((2 * kc + aS0) ^ aSw) << 4);
            uint32_t ah0, ah1, ah2, ah3, al0, al1, al2, al3;
            ldsm4(ah0, ah1, ah2, ah3, aHrb + offA);
            ldsm4(al0, al1, al2, al3, aLrb + offA);
            const uint32_t offB = (((2 * kc + bS) ^ bSw) << 4);
            #pragma unroll
            for (int kk = 0; kk < 2; kk++) {
                uint32_t bh0, bh1, bh2, bh3, bl0, bl1, bl2, bl3;
                ldsm4(bh0, bh1, bh2, bh3, bHrb + kk * 8192 + offB);
                ldsm4(bl0, bl1, bl2, bl3, bLrb + kk * 8192 + offB);
                mma16816(sc[2 * kk + 0], ah0, ah1, ah2, ah3, bh0, bh1);
                mma16816(sc[2 * kk + 1], ah0, ah1, ah2, ah3, bh2, bh3);
                mma16816(sc[2 * kk + 0], ah0, ah1, ah2, ah3, bl0, bl1);
                mma16816(sc[2 * kk + 1], ah0, ah1, ah2, ah3, bl2, bl3);
                mma16816(sc[2 * kk + 0], al0, al1, al2, al3, bh0, bh1);
                mma16816(sc[2 * kk + 1], al0, al1, al2, al3, bh2, bh3);
            }
        }

        // ---- online softmax: max reduce + lazy rescale
        float mx0 = -1e30f, mx1 = -1e30f;
        #pragma unroll
        for (int j = 0; j < 4; j++) {
            mx0 = fmaxf(mx0, fmaxf(sc[j][0], sc[j][1]));
            mx1 = fmaxf(mx1, fmaxf(sc[j][2], sc[j][3]));
        }
        mx0 = fmaxf(mx0, __shfl_xor_sync(0xffffffffu, mx0, 1));
        mx0 = fmaxf(mx0, __shfl_xor_sync(0xffffffffu, mx0, 2));
        mx1 = fmaxf(mx1, __shfl_xor_sync(0xffffffffu, mx1, 1));
        mx1 = fmaxf(mx1, __shfl_xor_sync(0xffffffffu, mx1, 2));
        const bool upd = (mx0 > m0) || (mx1 > m1);
        const float mn0 = fmaxf(m0, mx0), mn1 = fmaxf(m1, mx1);
        const float f0 = __expf(m0 - mn0), f1 = __expf(m1 - mn1);
        m0 = mn0; m1 = mn1;

        if (__any_sync(0xffffffffu, upd)) {
            #pragma unroll
            for (int nt = 0; nt < 32; nt++) {
                o[nt][0] *= f0; o[nt][1] *= f0;
                o[nt][2] *= f1; o[nt][3] *= f1;
            }
        }

        // ---- exp/pack interleaved with PV (per 16-key group)
        float s0 = 0.0f, s1 = 0.0f;
        #pragma unroll
        for (int kk = 0; kk < 2; kk++) {
            const int j0 = 2 * kk, j1 = 2 * kk + 1;
            float e00 = __expf(sc[j0][0] - mn0);
            float e01 = __expf(sc[j0][1] - mn0);
            float e10 = __expf(sc[j0][2] - mn1);
            float e11 = __expf(sc[j0][3] - mn1);
            float g00 = __expf(sc[j1][0] - mn0);
            float g01 = __expf(sc[j1][1] - mn0);
            float g10 = __expf(sc[j1][2] - mn1);
            float g11 = __expf(sc[j1][3] - mn1);
            s0 += (e00 + e01) + (g00 + g01);
            s1 += (e10 + e11) + (g10 + g11);
            const uint32_t p0 = h2pack(e00, e01);
            const uint32_t p1 = h2pack(e10, e11);
            const uint32_t p2 = h2pack(g00, g01);
            const uint32_t p3 = h2pack(g10, g11);
            #pragma unroll
            for (int q = 0; q < 16; q++) {
                const uint32_t offV = (((2 * q + vS) ^ vSw) << 4);
                uint32_t v0, v1, v2, v3;
                ldsm4t(v0, v1, v2, v3, vrb + kk * 8192 + offV);
                mma16816(o[2 * q + 0], p0, p1, p2, p3, v0, v1);
                mma16816(o[2 * q + 1], p0, p1, p2, p3, v2, v3);
            }
        }
        s0 += __shfl_xor_sync(0xffffffffu, s0, 1);
        s0 += __shfl_xor_sync(0xffffffffu, s0, 2);
        s1 += __shfl_xor_sync(0xffffffffu, s1, 1);
        s1 += __shfl_xor_sync(0xffffffffu, s1, 2);
        l0 = l0 * f0 + s0;
        l1 = l1 * f1 + s1;
    }

    // ---- epilogue: O /= l, store hi/lo fp16 pair
    const float inv0 = 1.0f / l0, inv1 = 1.0f / l1;
    const int row0 = n0 + wr0 + (lane >> 2);
    const size_t base = ((size_t)b * NTOK + row0) * CCH + ((lane & 3) << 1);
    __half* __restrict__ Yh0 = g_y_hi + base;
    __half* __restrict__ Yl0 = g_y_lo + base;
    #pragma unroll
    for (int nt = 0; nt < 32; nt++) {
        float v0 = o[nt][0] * inv0, v1 = o[nt][1] * inv0;
        float v2 = o[nt][2] * inv1, v3 = o[nt][3] * inv1;
        __half h0 = __float2half(v0), h1 = __float2half(v1);
        __half h2 = __float2half(v2), h3 = __float2half(v3);
        *(__half2*)(Yh0 + nt * 8)            = __halves2half2(h0, h1);
        *(__half2*)(Yh0 + nt * 8 + 8 * CCH)  = __halves2half2(h2, h3);
        *(__half2*)(Yl0 + nt * 8)            = __halves2half2(__float2half(v0 - __half2float(h0)),
                                                              __float2half(v1 - __half2float(h1)));
        *(__half2*)(Yl0 + nt * 8 + 8 * CCH)  = __halves2half2(__float2half(v2 - __half2float(h2)),
                                                              __float2half(v3 - __half2float(h3)));
    }
}

// =============================================================================
// out_tc: out[b,oc,n] = x + gamma * w_out @ Y   double-buffered k
// =============================================================================
#define OT_STG 40960

__device__ __forceinline__ void out_load_chunk(char* sb, const __half* Ah, const __half* Al,
                                               const __half* Bh, const __half* Bl,
                                               int m0, int n0, int k0, int t) {
    __half* sAh = (__half*)sb;
    __half* sAl = (__half*)(sb + 10240);
    __half* sBh = (__half*)(sb + 20480);
    __half* sBl = (__half*)(sb + 30720);
    const int r = t >> 1, hoff = (t & 1) * 16;
    cp16(smem_u32(sAh + r * PA_LD + hoff),     Ah + (m0 + r) * CCH + k0 + hoff);
    cp16(smem_u32(sAh + r * PA_LD + hoff + 8), Ah + (m0 + r) * CCH + k0 + hoff + 8);
    cp16(smem_u32(sAl + r * PA_LD + hoff),     Al + (m0 + r) * CCH + k0 + hoff);
    cp16(smem_u32(sAl + r * PA_LD + hoff + 8), Al + (m0 + r) * CCH + k0 + hoff + 8);
    cp16(smem_u32(sBh + r * PA_LD + hoff),     Bh + (size_t)(n0 + r) * CCH + k0 + hoff);
    cp16(smem_u32(sBh + r * PA_LD + hoff + 8), Bh + (size_t)(n0 + r) * CCH + k0 + hoff + 8);
    cp16(smem_u32(sBl + r * PA_LD + hoff),     Bl + (size_t)(n0 + r) * CCH + k0 + hoff);
    cp16(smem_u32(sBl + r * PA_LD + hoff + 8), Bl + (size_t)(n0 + r) * CCH + k0 + hoff + 8);
}

__global__ void __launch_bounds__(256) out_tc_kernel(const float* __restrict__ x,
                                                     const float* __restrict__ gamma,
                                                     float* __restrict__ out) {
    const int b  = blockIdx.z;
    const int n0 = blockIdx.x * 128;
    const int m0 = blockIdx.y * 128;

    const int t = threadIdx.x, lane = t & 31, warp = t >> 5;
    const int wr = warp & 3, wc = warp >> 2;

    const __half* __restrict__ Ah = g_w_hi + 3 * CCH * CCH;
    const __half* __restrict__ Al = g_w_lo + 3 * CCH * CCH;
    const __half* __restrict__ Bh = g_y_hi + (size_t)b * NTOK * CCH;
    const __half* __restrict__ Bl = g_y_lo + (size_t)b * NTOK * CCH;

    float acc[2][8][4] = {};
    const int gi = lane >> 3, li = lane & 7;
    const uint32_t aOff = (uint32_t)((wr * 32 + (lane & 15)) * PA_LD + ((lane >> 4) << 3)) * 2;
    const uint32_t bOff = (uint32_t)((wc * 64 + ((gi >> 1) << 3) + li) * PA_LD + ((gi & 1) << 3)) * 2;

    out_load_chunk(smem_raw, Ah, Al, Bh, Bl, m0, n0, 0, t);
    CP_COMMIT();

    for (int kc8 = 0; kc8 < 8; kc8++) {
        if (kc8 + 1 < 8) {
            out_load_chunk(smem_raw + ((kc8 + 1) & 1) * OT_STG, Ah, Al, Bh, Bl,
                           m0, n0, (kc8 + 1) * 32, t);
            CP_COMMIT();
            CP_WAIT(1);
        } else {
            CP_WAIT(0);
        }
        __syncthreads();

        char* sb = smem_raw + (kc8 & 1) * OT_STG;
        const uint32_t sAh32 = smem_u32(sb);
        const uint32_t sAl32 = smem_u32(sb + 10240);
        const uint32_t sBh32 = smem_u32(sb + 20480);
        const uint32_t sBl32 = smem_u32(sb + 30720);

        #pragma unroll
        for (int ks = 0; ks < 2; ks++) {
            const uint32_t ka = ks * 32;
            uint32_t ah[2][4], al[2][4];
            ldsm4(ah[0][0], ah[0][1], ah[0][2], ah[0][3], sAh32 + aOff + ka);
            ldsm4(ah[1][0], ah[1][1], ah[1][2], ah[1][3], sAh32 + aOff + ka + 16 * PA_LD * 2);
            ldsm4(al[0][0], al[0][1], al[0][2], al[0][3], sAl32 + aOff + ka);
            ldsm4(al[1][0], al[1][1], al[1][2], al[1][3], sAl32 + aOff + ka + 16 * PA_LD * 2);
            #pragma unroll
            for (int jn = 0; jn < 4; jn++) {
                uint32_t bhf[4], blf[4];
                ldsm4(bhf[0], bhf[1], bhf[2], bhf[3], sBh32 + bOff + ka + jn * 16 * PA_LD * 2);
                ldsm4(blf[0], blf[1], blf[2], blf[3], sBl32 + bOff + ka + jn * 16 * PA_LD * 2);
                #pragma unroll
                for (int mi = 0; mi < 2; mi++) {
                    mma16816(acc[mi][2 * jn + 0], ah[mi][0], ah[mi][1], ah[mi][2], ah[mi][3], bhf[0], bhf[1]);
                    mma16816(acc[mi][2 * jn + 1], ah[mi][0], ah[mi][1], ah[mi][2], ah[mi][3], bhf[2], bhf[3]);
                    mma16816(acc[mi][2 * jn + 0], ah[mi][0], ah[mi][1], ah[mi][2], ah[mi][3], blf[0], blf[1]);
                    mma16816(acc[mi][2 * jn + 1], ah[mi][0], ah[mi][1], ah[mi][2], ah[mi][3], blf[2], blf[3]);
                    mma16816(acc[mi][2 * jn + 0], al[mi][0], al[mi][1], al[mi][2], al[mi][3], bhf[0], bhf[1]);
                    mma16816(acc[mi][2 * jn + 1], al[mi][0], al[mi][1], al[mi][2], al[mi][3], bhf[2], bhf[3]);
                }
            }
        }
        __syncthreads();
    }

    const float gm = *gamma;
    const int mb = m0 + wr * 32 + (lane >> 2);
    const int nb = n0 + wc * 64 + (lane & 3) * 2;
    #pragma unroll
    for (int mi = 0; mi < 2; mi++)
        #pragma unroll
        for (int jn = 0; jn < 8; jn++) {
            const int m = mb + mi * 16, n = nb + jn * 8;
            {
                const size_t idx = ((size_t)b * CCH + m) * NTOK + n;
                float2 xv = *(const float2*)&x[idx];
                float2 r = {xv.x + gm * acc[mi][jn][0], xv.y + gm * acc[mi][jn][1]};
                *(float2*)&out[idx] = r;
            }
            {
                const size_t idx = ((size_t)b * CCH + m + 8) * NTOK + n;
                float2 xv = *(const float2*)&x[idx];
                float2 r = {xv.x + gm * acc[mi][jn][2], xv.y + gm * acc[mi][jn][3]};
                *(float2*)&out[idx] = r;
            }
        }
}

// =============================================================================
extern "C" void kernel_launch(void* const* d_in, const int* in_sizes, int n_in,
                              void* d_out, int out_size) {
    (void)in_sizes; (void)n_in; (void)out_size;
    const float* x      = (const float*)d_in[0];
    const float* w_th   = (const float*)d_in[1];
    const float* w_ph   = (const float*)d_in[2];
    const float* w_g    = (const float*)d_in[3];
    const float* w_out  = (const float*)d_in[4];
    const float* gamma  = (const float*)d_in[5];
    float* out = (float*)d_out;

    const int fsmem = 229376;          // Q 128K + K 2x32K + V 2x16K
    const int psmem = 2 * PJ_STG;
    const int osmem = 2 * OT_STG;
    cudaFuncSetAttribute(flash_kernel,   cudaFuncAttributeMaxDynamicSharedMemorySize, fsmem);
    cudaFuncSetAttribute(proj_tc_kernel, cudaFuncAttributeMaxDynamicSharedMemorySize, psmem);
    cudaFuncSetAttribute(out_tc_kernel,  cudaFuncAttributeMaxDynamicSharedMemorySize, osmem);

    split_all_kernel<<<4096 + 256, 256>>>(x, w_th, w_ph, w_g, w_out);
    proj_tc_kernel<<<dim3(NTOK / 128, CCH / 128, BSZ * 3), 256, psmem>>>();
    flash_kernel  <<<dim3(NTOK / BM, BSZ), 256, fsmem>>>();
    out_tc_kernel <<<dim3(NTOK / 128, CCH / 128, BSZ), 256, osmem>>>(x, gamma, out);
}

// round 11
// speedup vs baseline: 1.0505x; 1.0505x over previous
#include <cuda_runtime.h>
#include <cuda_fp16.h>
#include <cstdint>

#define BSZ  4
#define CCH  256
#define NTOK 4096

#define BM   128
#define BN   64

// ---------------- static device scratch (no allocation allowed) ----------------
__device__ __half g_th_hi[(size_t)BSZ * NTOK * CCH];
__device__ __half g_th_lo[(size_t)BSZ * NTOK * CCH];
__device__ __half g_ph_hi[(size_t)BSZ * NTOK * CCH];
__device__ __half g_ph_lo[(size_t)BSZ * NTOK * CCH];
__device__ __half g_gv  [(size_t)BSZ * NTOK * CCH];
__device__ __half g_y_hi[(size_t)BSZ * NTOK * CCH];
__device__ __half g_y_lo[(size_t)BSZ * NTOK * CCH];
__device__ __half g_x_hi[(size_t)BSZ * CCH * NTOK];
__device__ __half g_x_lo[(size_t)BSZ * CCH * NTOK];
__device__ __half g_w_hi[4 * CCH * CCH];
__device__ __half g_w_lo[4 * CCH * CCH];

// ---------------- PTX helpers ----------------
__device__ __forceinline__ uint32_t smem_u32(const void* p) {
    return (uint32_t)__cvta_generic_to_shared(p);
}
__device__ __forceinline__ void cp16(uint32_t s, const void* g) {
    asm volatile("cp.async.cg.shared.global [%0], [%1], 16;\n" :: "r"(s), "l"(g));
}
#define CP_COMMIT() asm volatile("cp.async.commit_group;\n" ::: "memory")
#define CP_WAIT(n)  asm volatile("cp.async.wait_group %0;\n" :: "n"(n) : "memory")

__device__ __forceinline__ void ldsm4(uint32_t& r0, uint32_t& r1, uint32_t& r2, uint32_t& r3,
                                      uint32_t a) {
    asm volatile("ldmatrix.sync.aligned.m8n8.x4.shared.b16 {%0,%1,%2,%3}, [%4];\n"
                 : "=r"(r0), "=r"(r1), "=r"(r2), "=r"(r3) : "r"(a));
}
__device__ __forceinline__ void ldsm4t(uint32_t& r0, uint32_t& r1, uint32_t& r2, uint32_t& r3,
                                       uint32_t a) {
    asm volatile("ldmatrix.sync.aligned.m8n8.x4.trans.shared.b16 {%0,%1,%2,%3}, [%4];\n"
                 : "=r"(r0), "=r"(r1), "=r"(r2), "=r"(r3) : "r"(a));
}
__device__ __forceinline__ void mma16816(float* c, uint32_t a0, uint32_t a1, uint32_t a2,
                                         uint32_t a3, uint32_t b0, uint32_t b1) {
    asm volatile("mma.sync.aligned.m16n8k16.row.col.f32.f16.f16.f32 "
                 "{%0,%1,%2,%3}, {%4,%5,%6,%7}, {%8,%9}, {%0,%1,%2,%3};\n"
                 : "+f"(c[0]), "+f"(c[1]), "+f"(c[2]), "+f"(c[3])
                 : "r"(a0), "r"(a1), "r"(a2), "r"(a3), "r"(b0), "r"(b1));
}
// fp16-accumulator MMA (2x rate) for split-fp16 correction terms
__device__ __forceinline__ void mma16816h(uint32_t* c, uint32_t a0, uint32_t a1, uint32_t a2,
                                          uint32_t a3, uint32_t b0, uint32_t b1) {
    asm volatile("mma.sync.aligned.m16n8k16.row.col.f16.f16.f16.f16 "
                 "{%0,%1}, {%2,%3,%4,%5}, {%6,%7}, {%0,%1};\n"
                 : "+r"(c[0]), "+r"(c[1])
                 : "r"(a0), "r"(a1), "r"(a2), "r"(a3), "r"(b0), "r"(b1));
}
__device__ __forceinline__ uint32_t h2pack(float a, float b) {
    __half2 h = __floats2half2_rn(a, b);
    return *reinterpret_cast<uint32_t*>(&h);
}

// ---- swizzled tile loaders: row stride 512B, 16B chunk c stored at (c ^ (row&7))
__device__ __forceinline__ void load_tile64_sw(char* dst, const __half* src, int t) {
    #pragma unroll
    for (int i = 0; i < 8; i++) {
        int idx = t + (i << 8);
        int r = idx >> 5, c = idx & 31;
        cp16(smem_u32(dst + r * 512 + ((c ^ (r & 7)) << 4)), src + (r << 8) + (c << 3));
    }
}
__device__ __forceinline__ void load_tile128_sw(char* dst, const __half* src, int t) {
    #pragma unroll
    for (int i = 0; i < 16; i++) {
        int idx = t + (i << 8);
        int r = idx >> 5, c = idx & 31;
        cp16(smem_u32(dst + r * 512 + ((c ^ (r & 7)) << 4)), src + (r << 8) + (c << 3));
    }
}

extern __shared__ char smem_raw[];

// =============================================================================
// Prep: split fp32 -> (hi, lo) fp16 pairs. One launch: x part + w part.
// =============================================================================
__global__ void split_all_kernel(const float* __restrict__ x,
                                 const float* __restrict__ w0, const float* __restrict__ w1,
                                 const float* __restrict__ w2, const float* __restrict__ w3) {
    const int blk = blockIdx.x;
    const float* __restrict__ src;
    __half *dhi, *dlo;
    int i;
    if (blk < 4096) {
        i = (blk * 256 + threadIdx.x) * 4;
        src = x; dhi = g_x_hi; dlo = g_x_lo;
    } else {
        const int wsel = (blk - 4096) >> 6;
        const int wblk = (blk - 4096) & 63;
        i = (wblk * 256 + threadIdx.x) * 4;
        src = (wsel == 0) ? w0 : (wsel == 1) ? w1 : (wsel == 2) ? w2 : w3;
        dhi = g_w_hi + wsel * CCH * CCH; dlo = g_w_lo + wsel * CCH * CCH;
    }
    float4 v = *(const float4*)&src[i];
    __half h0 = __float2half(v.x), h1 = __float2half(v.y);
    __half h2 = __float2half(v.z), h3 = __float2half(v.w);
    *(__half2*)&dhi[i]     = __halves2half2(h0, h1);
    *(__half2*)&dhi[i + 2] = __halves2half2(h2, h3);
    *(__half2*)&dlo[i]     = __halves2half2(__float2half(v.x - __half2float(h0)),
                                            __float2half(v.y - __half2float(h1)));
    *(__half2*)&dlo[i + 2] = __halves2half2(__float2half(v.z - __half2float(h2)),
                                            __float2half(v.w - __half2float(h3)));
}

// =============================================================================
// proj_tc: out[oc,n] = sum_c w[oc,c] * x[c,n]   split-fp16, double-buffered k
// =============================================================================
#define PA_LD 40
#define PB_LD 136
#define PJ_STG 38912

__device__ __forceinline__ void proj_load_chunk(char* sb, const __half* Ah, const __half* Al,
                                                const __half* Bh, const __half* Bl,
                                                int m0, int n0, int k0, int t) {
    __half* sAh = (__half*)sb;
    __half* sAl = (__half*)(sb + 10240);
    __half* sBh = (__half*)(sb + 20480);
    __half* sBl = (__half*)(sb + 29184);
    {
        const int r = t >> 1, hoff = (t & 1) * 16;
        cp16(smem_u32(sAh + r * PA_LD + hoff),     Ah + (m0 + r) * CCH + k0 + hoff);
        cp16(smem_u32(sAh + r * PA_LD + hoff + 8), Ah + (m0 + r) * CCH + k0 + hoff + 8);
        cp16(smem_u32(sAl + r * PA_LD + hoff),     Al + (m0 + r) * CCH + k0 + hoff);
        cp16(smem_u32(sAl + r * PA_LD + hoff + 8), Al + (m0 + r) * CCH + k0 + hoff + 8);
    }
    {
        const int r = t >> 3, hoff = (t & 7) * 16;
        cp16(smem_u32(sBh + r * PB_LD + hoff),     Bh + (size_t)(k0 + r) * NTOK + n0 + hoff);
        cp16(smem_u32(sBh + r * PB_LD + hoff + 8), Bh + (size_t)(k0 + r) * NTOK + n0 + hoff + 8);
        cp16(smem_u32(sBl + r * PB_LD + hoff),     Bl + (size_t)(k0 + r) * NTOK + n0 + hoff);
        cp16(smem_u32(sBl + r * PB_LD + hoff + 8), Bl + (size_t)(k0 + r) * NTOK + n0 + hoff + 8);
    }
}

__global__ void __launch_bounds__(256) proj_tc_kernel() {
    const int b  = blockIdx.z / 3;
    const int w  = blockIdx.z % 3;
    const int n0 = blockIdx.x * 128;
    const int m0 = blockIdx.y * 128;

    const int t = threadIdx.x, lane = t & 31, warp = t >> 5;
    const int wr = warp & 3, wc = warp >> 2;

    const __half* __restrict__ Ah = g_w_hi + w * CCH * CCH;
    const __half* __restrict__ Al = g_w_lo + w * CCH * CCH;
    const __half* __restrict__ Bh = g_x_hi + (size_t)b * CCH * NTOK;
    const __half* __restrict__ Bl = g_x_lo + (size_t)b * CCH * NTOK;

    float acc[2][8][4] = {};
    const int gi = lane >> 3, li = lane & 7;
    const uint32_t aOff = (uint32_t)((wr * 32 + (lane & 15)) * PA_LD + ((lane >> 4) << 3)) * 2;
    const uint32_t bOff = (uint32_t)((((gi & 1) << 3) + li) * PB_LD + wc * 64 + ((gi >> 1) << 3)) * 2;

    proj_load_chunk(smem_raw, Ah, Al, Bh, Bl, m0, n0, 0, t);
    CP_COMMIT();

    for (int kc8 = 0; kc8 < 8; kc8++) {
        if (kc8 + 1 < 8) {
            proj_load_chunk(smem_raw + ((kc8 + 1) & 1) * PJ_STG, Ah, Al, Bh, Bl,
                            m0, n0, (kc8 + 1) * 32, t);
            CP_COMMIT();
            CP_WAIT(1);
        } else {
            CP_WAIT(0);
        }
        __syncthreads();

        char* sb = smem_raw + (kc8 & 1) * PJ_STG;
        const uint32_t sAh32 = smem_u32(sb);
        const uint32_t sAl32 = smem_u32(sb + 10240);
        const uint32_t sBh32 = smem_u32(sb + 20480);
        const uint32_t sBl32 = smem_u32(sb + 29184);

        #pragma unroll
        for (int ks = 0; ks < 2; ks++) {
            const uint32_t ka = ks * 32, kb = ks * 16 * PB_LD * 2;
            uint32_t ah[2][4], al[2][4];
            ldsm4(ah[0][0], ah[0][1], ah[0][2], ah[0][3], sAh32 + aOff + ka);
            ldsm4(ah[1][0], ah[1][1], ah[1][2], ah[1][3], sAh32 + aOff + ka + 16 * PA_LD * 2);
            ldsm4(al[0][0], al[0][1], al[0][2], al[0][3], sAl32 + aOff + ka);
            ldsm4(al[1][0], al[1][1], al[1][2], al[1][3], sAl32 + aOff + ka + 16 * PA_LD * 2);
            #pragma unroll
            for (int jn = 0; jn < 4; jn++) {
                uint32_t bhf[4], blf[4];
                ldsm4t(bhf[0], bhf[1], bhf[2], bhf[3], sBh32 + bOff + kb + jn * 32);
                ldsm4t(blf[0], blf[1], blf[2], blf[3], sBl32 + bOff + kb + jn * 32);
                #pragma unroll
                for (int mi = 0; mi < 2; mi++) {
                    mma16816(acc[mi][2 * jn + 0], ah[mi][0], ah[mi][1], ah[mi][2], ah[mi][3], bhf[0], bhf[1]);
                    mma16816(acc[mi][2 * jn + 1], ah[mi][0], ah[mi][1], ah[mi][2], ah[mi][3], bhf[2], bhf[3]);
                    mma16816(acc[mi][2 * jn + 0], ah[mi][0], ah[mi][1], ah[mi][2], ah[mi][3], blf[0], blf[1]);
                    mma16816(acc[mi][2 * jn + 1], ah[mi][0], ah[mi][1], ah[mi][2], ah[mi][3], blf[2], blf[3]);
                    mma16816(acc[mi][2 * jn + 0], al[mi][0], al[mi][1], al[mi][2], al[mi][3], bhf[0], bhf[1]);
                    mma16816(acc[mi][2 * jn + 1], al[mi][0], al[mi][1], al[mi][2], al[mi][3], bhf[2], bhf[3]);
                }
            }
        }
        __syncthreads();
    }

    __half* buf = (__half*)smem_raw;   // [128 n][136]
    const int mb = wr * 32 + (lane >> 2);
    const int nb = wc * 64 + (lane & 3) * 2;
    const int npass = (w == 2) ? 1 : 2;

    for (int pass = 0; pass < npass; pass++) {
        __syncthreads();
        #pragma unroll
        for (int mi = 0; mi < 2; mi++)
            #pragma unroll
            for (int jn = 0; jn < 8; jn++)
                #pragma unroll
                for (int e = 0; e < 4; e++) {
                    const float v = acc[mi][jn][e];
                    const int nl = nb + jn * 8 + (e & 1);
                    const int ml = mb + mi * 16 + ((e >> 1) << 3);
                    __half h = __float2half(v);
                    buf[nl * PB_LD + ml] = (pass == 0) ? h : __float2half(v - __half2float(h));
                }
        __syncthreads();
        __half* __restrict__ G;
        if (w == 0) G = (pass == 0) ? g_th_hi : g_th_lo;
        else if (w == 1) G = (pass == 0) ? g_ph_hi : g_ph_lo;
        else G = g_gv;
        G += (size_t)b * NTOK * CCH;
        #pragma unroll
        for (int i = 0; i < 8; i++) {
            const int fi = t * 8 + i;
            const int row = fi >> 4, col8 = (fi & 15) * 8;
            *(float4*)&G[(size_t)(n0 + row) * CCH + m0 + col8] = *(float4*)&buf[row * PB_LD + col8];
        }
    }
}

// =============================================================================
// flash attention, BM=128, BN=64, swizzled smem, skip-rescale, exp/PV interleave
// QK corrections accumulate in fp16 (2x HMMA rate), folded per iteration.
// =============================================================================
__global__ void __launch_bounds__(256, 1) flash_kernel() {
    const int b  = blockIdx.y;
    const int n0 = blockIdx.x * BM;

    char* sQh = smem_raw;                 // 128 x 512B
    char* sQl = smem_raw + 65536;
    char* sKh = smem_raw + 131072;        // 64 x 512B
    char* sKl = smem_raw + 163840;
    char* sV  = smem_raw + 196608;

    const int t    = threadIdx.x;
    const int lane = t & 31;
    const int warp = t >> 5;
    const int wr0  = warp * 16;

    const __half* __restrict__ Qh = g_th_hi + ((size_t)b * NTOK + n0) * CCH;
    const __half* __restrict__ Ql = g_th_lo + ((size_t)b * NTOK + n0) * CCH;
    const __half* __restrict__ Kh = g_ph_hi + (size_t)b * NTOK * CCH;
    const __half* __restrict__ Kl = g_ph_lo + (size_t)b * NTOK * CCH;
    const __half* __restrict__ Vv = g_gv    + (size_t)b * NTOK * CCH;

    load_tile128_sw(sQh, Qh, t);
    load_tile128_sw(sQl, Ql, t);
    load_tile64_sw(sKh, Kh, t);
    load_tile64_sw(sKl, Kl, t);
    load_tile64_sw(sV,  Vv, t);
    CP_COMMIT();
    CP_WAIT(0);
    __syncthreads();

    const int gi = lane >> 3, li = lane & 7;
    const int arow = wr0 + (lane & 15);
    const uint32_t aSw = (uint32_t)(arow & 7);
    const uint32_t aS0 = (uint32_t)(lane >> 4);
    const uint32_t aHrb = smem_u32(sQh + arow * 512);
    const uint32_t aLrb = smem_u32(sQl + arow * 512);

    const int brow = ((gi >> 1) << 3) + li;
    const uint32_t bSw = (uint32_t)(brow & 7);
    const uint32_t bS  = (uint32_t)(gi & 1);
    const uint32_t bHrb = smem_u32(sKh + brow * 512);
    const uint32_t bLrb = smem_u32(sKl + brow * 512);

    const int vrow = ((gi & 1) << 3) + li;
    const uint32_t vSw = (uint32_t)(vrow & 7);
    const uint32_t vS  = (uint32_t)(gi >> 1);
    const uint32_t vrb = smem_u32(sV + vrow * 512);

    float o[32][4];
    #pragma unroll
    for (int nt = 0; nt < 32; nt++) { o[nt][0] = o[nt][1] = o[nt][2] = o[nt][3] = 0.0f; }
    float m0 = -1e30f, m1 = -1e30f, l0 = 0.0f, l1 = 0.0f;

    for (int it = 0; it < NTOK / BN; it++) {
        // ---- QK: S[16 x 64] per warp. hi*hi in fp32 acc; corrections in fp16 acc.
        float sc[8][4];
        uint32_t cacc[8][2];
        #pragma unroll
        for (int j = 0; j < 8; j++) {
            sc[j][0] = sc[j][1] = sc[j][2] = sc[j][3] = 0.0f;
            cacc[j][0] = cacc[j][1] = 0u;
        }

        #pragma unroll 4
        for (int kc = 0; kc < 16; kc++) {
            const uint32_t offA = (((2 * kc + aS0) ^ aSw) << 4);
            uint32_t ah0, ah1, ah2, ah3, al0, al1, al2, al3;
            ldsm4(ah0, ah1, ah2, ah3, aHrb + offA);
            ldsm4(al0, al1, al2, al3, aLrb + offA);
            const uint32_t offB = (((2 * kc + bS) ^ bSw) << 4);
            #pragma unroll
            for (int kk = 0; kk < 4; kk++) {
                uint32_t bh0, bh1, bh2, bh3, bl0, bl1, bl2, bl3;
                ldsm4(bh0, bh1, bh2, bh3, bHrb + kk * 8192 + offB);
                ldsm4(bl0, bl1, bl2, bl3, bLrb + kk * 8192 + offB);
                mma16816(sc[2 * kk + 0], ah0, ah1, ah2, ah3, bh0, bh1);
                mma16816(sc[2 * kk + 1], ah0, ah1, ah2, ah3, bh2, bh3);
                mma16816h(cacc[2 * kk + 0], ah0, ah1, ah2, ah3, bl0, bl1);
                mma16816h(cacc[2 * kk + 1], ah0, ah1, ah2, ah3, bl2, bl3);
                mma16816h(cacc[2 * kk + 0], al0, al1, al2, al3, bh0, bh1);
                mma16816h(cacc[2 * kk + 1], al0, al1, al2, al3, bh2, bh3);
            }
        }

        // fold fp16 corrections into fp32 scores
        #pragma unroll
        for (int j = 0; j < 8; j++) {
            float2 c01 = __half22float2(*(__half2*)&cacc[j][0]);
            float2 c23 = __half22float2(*(__half2*)&cacc[j][1]);
            sc[j][0] += c01.x; sc[j][1] += c01.y;
            sc[j][2] += c23.x; sc[j][3] += c23.y;
        }

        CP_WAIT(0);           // V(it) complete
        __syncthreads();      // all warps done reading sK

        if (it + 1 < NTOK / BN) {
            load_tile64_sw(sKh, Kh + (size_t)(it + 1) * BN * CCH, t);
            load_tile64_sw(sKl, Kl + (size_t)(it + 1) * BN * CCH, t);
            CP_COMMIT();
        }

        // ---- online softmax: max reduce + lazy rescale
        float mx0 = -1e30f, mx1 = -1e30f;
        #pragma unroll
        for (int j = 0; j < 8; j++) {
            mx0 = fmaxf(mx0, fmaxf(sc[j][0], sc[j][1]));
            mx1 = fmaxf(mx1, fmaxf(sc[j][2], sc[j][3]));
        }
        mx0 = fmaxf(mx0, __shfl_xor_sync(0xffffffffu, mx0, 1));
        mx0 = fmaxf(mx0, __shfl_xor_sync(0xffffffffu, mx0, 2));
        mx1 = fmaxf(mx1, __shfl_xor_sync(0xffffffffu, mx1, 1));
        mx1 = fmaxf(mx1, __shfl_xor_sync(0xffffffffu, mx1, 2));
        const bool upd = (mx0 > m0) || (mx1 > m1);
        const float mn0 = fmaxf(m0, mx0), mn1 = fmaxf(m1, mx1);
        const float f0 = __expf(m0 - mn0), f1 = __expf(m1 - mn1);
        m0 = mn0; m1 = mn1;

        if (__any_sync(0xffffffffu, upd)) {
            #pragma unroll
            for (int nt = 0; nt < 32; nt++) {
                o[nt][0] *= f0; o[nt][1] *= f0;
                o[nt][2] *= f1; o[nt][3] *= f1;
            }
        }

        // ---- exp/pack interleaved with PV (per 16-key group)
        float s0 = 0.0f, s1 = 0.0f;
        #pragma unroll
        for (int kk = 0; kk < 4; kk++) {
            const int j0 = 2 * kk, j1 = 2 * kk + 1;
            float e00 = __expf(sc[j0][0] - mn0);
            float e01 = __expf(sc[j0][1] - mn0);
            float e10 = __expf(sc[j0][2] - mn1);
            float e11 = __expf(sc[j0][3] - mn1);
            float g00 = __expf(sc[j1][0] - mn0);
            float g01 = __expf(sc[j1][1] - mn0);
            float g10 = __expf(sc[j1][2] - mn1);
            float g11 = __expf(sc[j1][3] - mn1);
            s0 += (e00 + e01) + (g00 + g01);
            s1 += (e10 + e11) + (g10 + g11);
            const uint32_t p0 = h2pack(e00, e01);
            const uint32_t p1 = h2pack(e10, e11);
            const uint32_t p2 = h2pack(g00, g01);
            const uint32_t p3 = h2pack(g10, g11);
            #pragma unroll
            for (int q = 0; q < 16; q++) {
                const uint32_t offV = (((2 * q + vS) ^ vSw) << 4);
                uint32_t v0, v1, v2, v3;
                ldsm4t(v0, v1, v2, v3, vrb + kk * 8192 + offV);
                mma16816(o[2 * q + 0], p0, p1, p2, p3, v0, v1);
                mma16816(o[2 * q + 1], p0, p1, p2, p3, v2, v3);
            }
        }
        s0 += __shfl_xor_sync(0xffffffffu, s0, 1);
        s0 += __shfl_xor_sync(0xffffffffu, s0, 2);
        s1 += __shfl_xor_sync(0xffffffffu, s1, 1);
        s1 += __shfl_xor_sync(0xffffffffu, s1, 2);
        l0 = l0 * f0 + s0;
        l1 = l1 * f1 + s1;

        __syncthreads();      // all warps done reading sV
        if (it + 1 < NTOK / BN) {
            load_tile64_sw(sV, Vv + (size_t)(it + 1) * BN * CCH, t);
            CP_COMMIT();
            CP_WAIT(1);       // K(it+1) complete; V(it+1) may stay in flight
        }
        __syncthreads();
    }

    // ---- epilogue: O /= l, store hi/lo fp16 pair
    const float inv0 = 1.0f / l0, inv1 = 1.0f / l1;
    const int row0 = n0 + wr0 + (lane >> 2);
    const size_t base = ((size_t)b * NTOK + row0) * CCH + ((lane & 3) << 1);
    __half* __restrict__ Yh0 = g_y_hi + base;
    __half* __restrict__ Yl0 = g_y_lo + base;
    #pragma unroll
    for (int nt = 0; nt < 32; nt++) {
        float v0 = o[nt][0] * inv0, v1 = o[nt][1] * inv0;
        float v2 = o[nt][2] * inv1, v3 = o[nt][3] * inv1;
        __half h0 = __float2half(v0), h1 = __float2half(v1);
        __half h2 = __float2half(v2), h3 = __float2half(v3);
        *(__half2*)(Yh0 + nt * 8)            = __halves2half2(h0, h1);
        *(__half2*)(Yh0 + nt * 8 + 8 * CCH)  = __halves2half2(h2, h3);
        *(__half2*)(Yl0 + nt * 8)            = __halves2half2(__float2half(v0 - __half2float(h0)),
                                                              __float2half(v1 - __half2float(h1)));
        *(__half2*)(Yl0 + nt * 8 + 8 * CCH)  = __halves2half2(__float2half(v2 - __half2float(h2)),
                                                              __float2half(v3 - __half2float(h3)));
    }
}

// =============================================================================
// out_tc: out[b,oc,n] = x + gamma * w_out @ Y   double-buffered k
// =============================================================================
#define OT_STG 40960

__device__ __forceinline__ void out_load_chunk(char* sb, const __half* Ah, const __half* Al,
                                               const __half* Bh, const __half* Bl,
                                               int m0, int n0, int k0, int t) {
    __half* sAh = (__half*)sb;
    __half* sAl = (__half*)(sb + 10240);
    __half* sBh = (__half*)(sb + 20480);
    __half* sBl = (__half*)(sb + 30720);
    const int r = t >> 1, hoff = (t & 1) * 16;
    cp16(smem_u32(sAh + r * PA_LD + hoff),     Ah + (m0 + r) * CCH + k0 + hoff);
    cp16(smem_u32(sAh + r * PA_LD + hoff + 8), Ah + (m0 + r) * CCH + k0 + hoff + 8);
    cp16(smem_u32(sAl + r * PA_LD + hoff),     Al + (m0 + r) * CCH + k0 + hoff);
    cp16(smem_u32(sAl + r * PA_LD + hoff + 8), Al + (m0 + r) * CCH + k0 + hoff + 8);
    cp16(smem_u32(sBh + r * PA_LD + hoff),     Bh + (size_t)(n0 + r) * CCH + k0 + hoff);
    cp16(smem_u32(sBh + r * PA_LD + hoff + 8), Bh + (size_t)(n0 + r) * CCH + k0 + hoff + 8);
    cp16(smem_u32(sBl + r * PA_LD + hoff),     Bl + (size_t)(n0 + r) * CCH + k0 + hoff);
    cp16(smem_u32(sBl + r * PA_LD + hoff + 8), Bl + (size_t)(n0 + r) * CCH + k0 + hoff + 8);
}

__global__ void __launch_bounds__(256) out_tc_kernel(const float* __restrict__ x,
                                                     const float* __restrict__ gamma,
                                                     float* __restrict__ out) {
    const int b  = blockIdx.z;
    const int n0 = blockIdx.x * 128;
    const int m0 = blockIdx.y * 128;

    const int t = threadIdx.x, lane = t & 31, warp = t >> 5;
    const int wr = warp & 3, wc = warp >> 2;

    const __half* __restrict__ Ah = g_w_hi + 3 * CCH * CCH;
    const __half* __restrict__ Al = g_w_lo + 3 * CCH * CCH;
    const __half* __restrict__ Bh = g_y_hi + (size_t)b * NTOK * CCH;
    const __half* __restrict__ Bl = g_y_lo + (size_t)b * NTOK * CCH;

    float acc[2][8][4] = {};
    const int gi = lane >> 3, li = lane & 7;
    const uint32_t aOff = (uint32_t)((wr * 32 + (lane & 15)) * PA_LD + ((lane >> 4) << 3)) * 2;
    const uint32_t bOff = (uint32_t)((wc * 64 + ((gi >> 1) << 3) + li) * PA_LD + ((gi & 1) << 3)) * 2;

    out_load_chunk(smem_raw, Ah, Al, Bh, Bl, m0, n0, 0, t);
    CP_COMMIT();

    for (int kc8 = 0; kc8 < 8; kc8++) {
        if (kc8 + 1 < 8) {
            out_load_chunk(smem_raw + ((kc8 + 1) & 1) * OT_STG, Ah, Al, Bh, Bl,
                           m0, n0, (kc8 + 1) * 32, t);
            CP_COMMIT();
            CP_WAIT(1);
        } else {
            CP_WAIT(0);
        }
        __syncthreads();

        char* sb = smem_raw + (kc8 & 1) * OT_STG;
        const uint32_t sAh32 = smem_u32(sb);
        const uint32_t sAl32 = smem_u32(sb + 10240);
        const uint32_t sBh32 = smem_u32(sb + 20480);
        const uint32_t sBl32 = smem_u32(sb + 30720);

        #pragma unroll
        for (int ks = 0; ks < 2; ks++) {
            const uint32_t ka = ks * 32;
            uint32_t ah[2][4], al[2][4];
            ldsm4(ah[0][0], ah[0][1], ah[0][2], ah[0][3], sAh32 + aOff + ka);
            ldsm4(ah[1][0], ah[1][1], ah[1][2], ah[1][3], sAh32 + aOff + ka + 16 * PA_LD * 2);
            ldsm4(al[0][0], al[0][1], al[0][2], al[0][3], sAl32 + aOff + ka);
            ldsm4(al[1][0], al[1][1], al[1][2], al[1][3], sAl32 + aOff + ka + 16 * PA_LD * 2);
            #pragma unroll
            for (int jn = 0; jn < 4; jn++) {
                uint32_t bhf[4], blf[4];
                ldsm4(bhf[0], bhf[1], bhf[2], bhf[3], sBh32 + bOff + ka + jn * 16 * PA_LD * 2);
                ldsm4(blf[0], blf[1], blf[2], blf[3], sBl32 + bOff + ka + jn * 16 * PA_LD * 2);
                #pragma unroll
                for (int mi = 0; mi < 2; mi++) {
                    mma16816(acc[mi][2 * jn + 0], ah[mi][0], ah[mi][1], ah[mi][2], ah[mi][3], bhf[0], bhf[1]);
                    mma16816(acc[mi][2 * jn + 1], ah[mi][0], ah[mi][1], ah[mi][2], ah[mi][3], bhf[2], bhf[3]);
                    mma16816(acc[mi][2 * jn + 0], ah[mi][0], ah[mi][1], ah[mi][2], ah[mi][3], blf[0], blf[1]);
                    mma16816(acc[mi][2 * jn + 1], ah[mi][0], ah[mi][1], ah[mi][2], ah[mi][3], blf[2], blf[3]);
                    mma16816(acc[mi][2 * jn + 0], al[mi][0], al[mi][1], al[mi][2], al[mi][3], bhf[0], bhf[1]);
                    mma16816(acc[mi][2 * jn + 1], al[mi][0], al[mi][1], al[mi][2], al[mi][3], bhf[2], bhf[3]);
                }
            }
        }
        __syncthreads();
    }

    const float gm = *gamma;
    const int mb = m0 + wr * 32 + (lane >> 2);
    const int nb = n0 + wc * 64 + (lane & 3) * 2;
    #pragma unroll
    for (int mi = 0; mi < 2; mi++)
        #pragma unroll
        for (int jn = 0; jn < 8; jn++) {
            const int m = mb + mi * 16, n = nb + jn * 8;
            {
                const size_t idx = ((size_t)b * CCH + m) * NTOK + n;
                float2 xv = *(const float2*)&x[idx];
                float2 r = {xv.x + gm * acc[mi][jn][0], xv.y + gm * acc[mi][jn][1]};
                *(float2*)&out[idx] = r;
            }
            {
                const size_t idx = ((size_t)b * CCH + m + 8) * NTOK + n;
                float2 xv = *(const float2*)&x[idx];
                float2 r = {xv.x + gm * acc[mi][jn][2], xv.y + gm * acc[mi][jn][3]};
                *(float2*)&out[idx] = r;
            }
        }
}

// =============================================================================
extern "C" void kernel_launch(void* const* d_in, const int* in_sizes, int n_in,
                              void* d_out, int out_size) {
    (void)in_sizes; (void)n_in; (void)out_size;
    const float* x      = (const float*)d_in[0];
    const float* w_th   = (const float*)d_in[1];
    const float* w_ph   = (const float*)d_in[2];
    const float* w_g    = (const float*)d_in[3];
    const float* w_out  = (const float*)d_in[4];
    const float* gamma  = (const float*)d_in[5];
    float* out = (float*)d_out;

    const int fsmem = 229376;
    const int psmem = 2 * PJ_STG;
    const int osmem = 2 * OT_STG;
    cudaFuncSetAttribute(flash_kernel,   cudaFuncAttributeMaxDynamicSharedMemorySize, fsmem);
    cudaFuncSetAttribute(proj_tc_kernel, cudaFuncAttributeMaxDynamicSharedMemorySize, psmem);
    cudaFuncSetAttribute(out_tc_kernel,  cudaFuncAttributeMaxDynamicSharedMemorySize, osmem);

    split_all_kernel<<<4096 + 256, 256>>>(x, w_th, w_ph, w_g, w_out);
    proj_tc_kernel<<<dim3(NTOK / 128, CCH / 128, BSZ * 3), 256, psmem>>>();
    flash_kernel  <<<dim3(NTOK / BM, BSZ), 256, fsmem>>>();
    out_tc_kernel <<<dim3(NTOK / 128, CCH / 128, BSZ), 256, osmem>>>(x, gamma, out);
}

// round 13
// speedup vs baseline: 1.2689x; 1.2080x over previous
#include <cuda_runtime.h>
#include <cuda_fp16.h>
#include <cstdint>

#define BSZ  4
#define CCH  256
#define NTOK 4096

#define BM   128
#define BN   64

// ---------------- static device scratch (no allocation allowed) ----------------
__device__ __half g_th_hi[(size_t)BSZ * NTOK * CCH];
__device__ __half g_th_lo[(size_t)BSZ * NTOK * CCH];
__device__ __half g_ph_hi[(size_t)BSZ * NTOK * CCH];
__device__ __half g_gv  [(size_t)BSZ * NTOK * CCH];
__device__ __half g_y_hi[(size_t)BSZ * NTOK * CCH];
__device__ __half g_y_lo[(size_t)BSZ * NTOK * CCH];
__device__ __half g_x_hi[(size_t)BSZ * CCH * NTOK];
__device__ __half g_x_lo[(size_t)BSZ * CCH * NTOK];
__device__ __half g_w_hi[4 * CCH * CCH];
__device__ __half g_w_lo[4 * CCH * CCH];

// ---------------- PTX helpers ----------------
__device__ __forceinline__ uint32_t smem_u32(const void* p) {
    return (uint32_t)__cvta_generic_to_shared(p);
}
__device__ __forceinline__ void cp16(uint32_t s, const void* g) {
    asm volatile("cp.async.cg.shared.global [%0], [%1], 16;\n" :: "r"(s), "l"(g));
}
#define CP_COMMIT() asm volatile("cp.async.commit_group;\n" ::: "memory")
#define CP_WAIT(n)  asm volatile("cp.async.wait_group %0;\n" :: "n"(n) : "memory")

__device__ __forceinline__ void ldsm4(uint32_t& r0, uint32_t& r1, uint32_t& r2, uint32_t& r3,
                                      uint32_t a) {
    asm volatile("ldmatrix.sync.aligned.m8n8.x4.shared.b16 {%0,%1,%2,%3}, [%4];\n"
                 : "=r"(r0), "=r"(r1), "=r"(r2), "=r"(r3) : "r"(a));
}
__device__ __forceinline__ void ldsm4t(uint32_t& r0, uint32_t& r1, uint32_t& r2, uint32_t& r3,
                                       uint32_t a) {
    asm volatile("ldmatrix.sync.aligned.m8n8.x4.trans.shared.b16 {%0,%1,%2,%3}, [%4];\n"
                 : "=r"(r0), "=r"(r1), "=r"(r2), "=r"(r3) : "r"(a));
}
__device__ __forceinline__ void mma16816(float* c, uint32_t a0, uint32_t a1, uint32_t a2,
                                         uint32_t a3, uint32_t b0, uint32_t b1) {
    asm volatile("mma.sync.aligned.m16n8k16.row.col.f32.f16.f16.f32 "
                 "{%0,%1,%2,%3}, {%4,%5,%6,%7}, {%8,%9}, {%0,%1,%2,%3};\n"
                 : "+f"(c[0]), "+f"(c[1]), "+f"(c[2]), "+f"(c[3])
                 : "r"(a0), "r"(a1), "r"(a2), "r"(a3), "r"(b0), "r"(b1));
}
// fp16-accumulator MMA (2x rate) for the split-fp16 correction term
__device__ __forceinline__ void mma16816h(uint32_t* c, uint32_t a0, uint32_t a1, uint32_t a2,
                                          uint32_t a3, uint32_t b0, uint32_t b1) {
    asm volatile("mma.sync.aligned.m16n8k16.row.col.f16.f16.f16.f16 "
                 "{%0,%1}, {%2,%3,%4,%5}, {%6,%7}, {%0,%1};\n"
                 : "+r"(c[0]), "+r"(c[1])
                 : "r"(a0), "r"(a1), "r"(a2), "r"(a3), "r"(b0), "r"(b1));
}
__device__ __forceinline__ uint32_t h2pack(float a, float b) {
    __half2 h = __floats2half2_rn(a, b);
    return *reinterpret_cast<uint32_t*>(&h);
}

// ---- swizzled tile loaders: row stride 512B, 16B chunk c stored at (c ^ (row&7))
__device__ __forceinline__ void load_tile64_sw(char* dst, const __half* src, int t) {
    #pragma unroll
    for (int i = 0; i < 8; i++) {
        int idx = t + (i << 8);
        int r = idx >> 5, c = idx & 31;
        cp16(smem_u32(dst + r * 512 + ((c ^ (r & 7)) << 4)), src + (r << 8) + (c << 3));
    }
}
__device__ __forceinline__ void load_tile128_sw(char* dst, const __half* src, int t) {
    #pragma unroll
    for (int i = 0; i < 16; i++) {
        int idx = t + (i << 8);
        int r = idx >> 5, c = idx & 31;
        cp16(smem_u32(dst + r * 512 + ((c ^ (r & 7)) << 4)), src + (r << 8) + (c << 3));
    }
}

extern __shared__ char smem_raw[];

// =============================================================================
// Prep: split fp32 -> (hi, lo) fp16 pairs. One launch: x part + w part.
// =============================================================================
__global__ void split_all_kernel(const float* __restrict__ x,
                                 const float* __restrict__ w0, const float* __restrict__ w1,
                                 const float* __restrict__ w2, const float* __restrict__ w3) {
    const int blk = blockIdx.x;
    const float* __restrict__ src;
    __half *dhi, *dlo;
    int i;
    if (blk < 4096) {
        i = (blk * 256 + threadIdx.x) * 4;
        src = x; dhi = g_x_hi; dlo = g_x_lo;
    } else {
        const int wsel = (blk - 4096) >> 6;
        const int wblk = (blk - 4096) & 63;
        i = (wblk * 256 + threadIdx.x) * 4;
        src = (wsel == 0) ? w0 : (wsel == 1) ? w1 : (wsel == 2) ? w2 : w3;
        dhi = g_w_hi + wsel * CCH * CCH; dlo = g_w_lo + wsel * CCH * CCH;
    }
    float4 v = *(const float4*)&src[i];
    __half h0 = __float2half(v.x), h1 = __float2half(v.y);
    __half h2 = __float2half(v.z), h3 = __float2half(v.w);
    *(__half2*)&dhi[i]     = __halves2half2(h0, h1);
    *(__half2*)&dhi[i + 2] = __halves2half2(h2, h3);
    *(__half2*)&dlo[i]     = __halves2half2(__float2half(v.x - __half2float(h0)),
                                            __float2half(v.y - __half2float(h1)));
    *(__half2*)&dlo[i + 2] = __halves2half2(__float2half(v.z - __half2float(h2)),
                                            __float2half(v.w - __half2float(h3)));
}

// =============================================================================
// proj_tc: out[oc,n] = sum_c w[oc,c] * x[c,n]   split-fp16, double-buffered k
// theta (w=0): hi+lo out.  phi (w=1): hi only.  g (w=2): fp16 out.
// =============================================================================
#define PA_LD 40
#define PB_LD 136
#define PJ_STG 38912

__device__ __forceinline__ void proj_load_chunk(char* sb, const __half* Ah, const __half* Al,
                                                const __half* Bh, const __half* Bl,
                                                int m0, int n0, int k0, int t) {
    __half* sAh = (__half*)sb;
    __half* sAl = (__half*)(sb + 10240);
    __half* sBh = (__half*)(sb + 20480);
    __half* sBl = (__half*)(sb + 29184);
    {
        const int r = t >> 1, hoff = (t & 1) * 16;
        cp16(smem_u32(sAh + r * PA_LD + hoff),     Ah + (m0 + r) * CCH + k0 + hoff);
        cp16(smem_u32(sAh + r * PA_LD + hoff + 8), Ah + (m0 + r) * CCH + k0 + hoff + 8);
        cp16(smem_u32(sAl + r * PA_LD + hoff),     Al + (m0 + r) * CCH + k0 + hoff);
        cp16(smem_u32(sAl + r * PA_LD + hoff + 8), Al + (m0 + r) * CCH + k0 + hoff + 8);
    }
    {
        const int r = t >> 3, hoff = (t & 7) * 16;
        cp16(smem_u32(sBh + r * PB_LD + hoff),     Bh + (size_t)(k0 + r) * NTOK + n0 + hoff);
        cp16(smem_u32(sBh + r * PB_LD + hoff + 8), Bh + (size_t)(k0 + r) * NTOK + n0 + hoff + 8);
        cp16(smem_u32(sBl + r * PB_LD + hoff),     Bl + (size_t)(k0 + r) * NTOK + n0 + hoff);
        cp16(smem_u32(sBl + r * PB_LD + hoff + 8), Bl + (size_t)(k0 + r) * NTOK + n0 + hoff + 8);
    }
}

__global__ void __launch_bounds__(256) proj_tc_kernel() {
    const int b  = blockIdx.z / 3;
    const int w  = blockIdx.z % 3;
    const int n0 = blockIdx.x * 128;
    const int m0 = blockIdx.y * 128;

    const int t = threadIdx.x, lane = t & 31, warp = t >> 5;
    const int wr = warp & 3, wc = warp >> 2;

    const __half* __restrict__ Ah = g_w_hi + w * CCH * CCH;
    const __half* __restrict__ Al = g_w_lo + w * CCH * CCH;
    const __half* __restrict__ Bh = g_x_hi + (size_t)b * CCH * NTOK;
    const __half* __restrict__ Bl = g_x_lo + (size_t)b * CCH * NTOK;

    float acc[2][8][4] = {};
    const int gi = lane >> 3, li = lane & 7;
    const uint32_t aOff = (uint32_t)((wr * 32 + (lane & 15)) * PA_LD + ((lane >> 4) << 3)) * 2;
    const uint32_t bOff = (uint32_t)((((gi & 1) << 3) + li) * PB_LD + wc * 64 + ((gi >> 1) << 3)) * 2;

    proj_load_chunk(smem_raw, Ah, Al, Bh, Bl, m0, n0, 0, t);
    CP_COMMIT();

    for (int kc8 = 0; kc8 < 8; kc8++) {
        if (kc8 + 1 < 8) {
            proj_load_chunk(smem_raw + ((kc8 + 1) & 1) * PJ_STG, Ah, Al, Bh, Bl,
                            m0, n0, (kc8 + 1) * 32, t);
            CP_COMMIT();
            CP_WAIT(1);
        } else {
            CP_WAIT(0);
        }
        __syncthreads();

        char* sb = smem_raw + (kc8 & 1) * PJ_STG;
        const uint32_t sAh32 = smem_u32(sb);
        const uint32_t sAl32 = smem_u32(sb + 10240);
        const uint32_t sBh32 = smem_u32(sb + 20480);
        const uint32_t sBl32 = smem_u32(sb + 29184);

        #pragma unroll
        for (int ks = 0; ks < 2; ks++) {
            const uint32_t ka = ks * 32, kb = ks * 16 * PB_LD * 2;
            uint32_t ah[2][4], al[2][4];
            ldsm4(ah[0][0], ah[0][1], ah[0][2], ah[0][3], sAh32 + aOff + ka);
            ldsm4(ah[1][0], ah[1][1], ah[1][2], ah[1][3], sAh32 + aOff + ka + 16 * PA_LD * 2);
            ldsm4(al[0][0], al[0][1], al[0][2], al[0][3], sAl32 + aOff + ka);
            ldsm4(al[1][0], al[1][1], al[1][2], al[1][3], sAl32 + aOff + ka + 16 * PA_LD * 2);
            #pragma unroll
            for (int jn = 0; jn < 4; jn++) {
                uint32_t bhf[4], blf[4];
                ldsm4t(bhf[0], bhf[1], bhf[2], bhf[3], sBh32 + bOff + kb + jn * 32);
                ldsm4t(blf[0], blf[1], blf[2], blf[3], sBl32 + bOff + kb + jn * 32);
                #pragma unroll
                for (int mi = 0; mi < 2; mi++) {
                    mma16816(acc[mi][2 * jn + 0], ah[mi][0], ah[mi][1], ah[mi][2], ah[mi][3], bhf[0], bhf[1]);
                    mma16816(acc[mi][2 * jn + 1], ah[mi][0], ah[mi][1], ah[mi][2], ah[mi][3], bhf[2], bhf[3]);
                    mma16816(acc[mi][2 * jn + 0], ah[mi][0], ah[mi][1], ah[mi][2], ah[mi][3], blf[0], blf[1]);
                    mma16816(acc[mi][2 * jn + 1], ah[mi][0], ah[mi][1], ah[mi][2], ah[mi][3], blf[2], blf[3]);
                    mma16816(acc[mi][2 * jn + 0], al[mi][0], al[mi][1], al[mi][2], al[mi][3], bhf[0], bhf[1]);
                    mma16816(acc[mi][2 * jn + 1], al[mi][0], al[mi][1], al[mi][2], al[mi][3], bhf[2], bhf[3]);
                }
            }
        }
        __syncthreads();
    }

    __half* buf = (__half*)smem_raw;   // [128 n][136]
    const int mb = wr * 32 + (lane >> 2);
    const int nb = wc * 64 + (lane & 3) * 2;
    const int npass = (w == 0) ? 2 : 1;

    for (int pass = 0; pass < npass; pass++) {
        __syncthreads();
        #pragma unroll
        for (int mi = 0; mi < 2; mi++)
            #pragma unroll
            for (int jn = 0; jn < 8; jn++)
                #pragma unroll
                for (int e = 0; e < 4; e++) {
                    const float v = acc[mi][jn][e];
                    const int nl = nb + jn * 8 + (e & 1);
                    const int ml = mb + mi * 16 + ((e >> 1) << 3);
                    __half h = __float2half(v);
                    buf[nl * PB_LD + ml] = (pass == 0) ? h : __float2half(v - __half2float(h));
                }
        __syncthreads();
        __half* __restrict__ G;
        if (w == 0) G = (pass == 0) ? g_th_hi : g_th_lo;
        else if (w == 1) G = g_ph_hi;
        else G = g_gv;
        G += (size_t)b * NTOK * CCH;
        #pragma unroll
        for (int i = 0; i < 8; i++) {
            const int fi = t * 8 + i;
            const int row = fi >> 4, col8 = (fi & 15) * 8;
            *(float4*)&G[(size_t)(n0 + row) * CCH + m0 + col8] = *(float4*)&buf[row * PB_LD + col8];
        }
    }
}

// =============================================================================
// flash attention, BM=128, BN=64. S = th_hi*ph_hi (fp32) + th_lo*ph_hi (fp16 acc).
// phi-lo never touched: K-lo tiles/loads eliminated (-29% LDS).
// smem 192K: Qh 0 | Ql 64K | Kh 128K (32K) | V 160K (32K)
// =============================================================================
__global__ void __launch_bounds__(256, 1) flash_kernel() {
    const int b  = blockIdx.y;
    const int n0 = blockIdx.x * BM;

    char* sQh = smem_raw;
    char* sQl = smem_raw + 65536;
    char* sKh = smem_raw + 131072;
    char* sV  = smem_raw + 163840;

    const int t    = threadIdx.x;
    const int lane = t & 31;
    const int warp = t >> 5;
    const int wr0  = warp * 16;

    const __half* __restrict__ Qh = g_th_hi + ((size_t)b * NTOK + n0) * CCH;
    const __half* __restrict__ Ql = g_th_lo + ((size_t)b * NTOK + n0) * CCH;
    const __half* __restrict__ Kh = g_ph_hi + (size_t)b * NTOK * CCH;
    const __half* __restrict__ Vv = g_gv    + (size_t)b * NTOK * CCH;

    load_tile128_sw(sQh, Qh, t);
    load_tile128_sw(sQl, Ql, t);
    load_tile64_sw(sKh, Kh, t);
    load_tile64_sw(sV,  Vv, t);
    CP_COMMIT();
    CP_WAIT(0);
    __syncthreads();

    const int gi = lane >> 3, li = lane & 7;
    const int arow = wr0 + (lane & 15);
    const uint32_t aSw = (uint32_t)(arow & 7);
    const uint32_t aS0 = (uint32_t)(lane >> 4);
    const uint32_t aHrb = smem_u32(sQh + arow * 512);
    const uint32_t aLrb = smem_u32(sQl + arow * 512);

    const int brow = ((gi >> 1) << 3) + li;
    const uint32_t bSw = (uint32_t)(brow & 7);
    const uint32_t bS  = (uint32_t)(gi & 1);
    const uint32_t bHrb = smem_u32(sKh + brow * 512);

    const int vrow = ((gi & 1) << 3) + li;
    const uint32_t vSw = (uint32_t)(vrow & 7);
    const uint32_t vS  = (uint32_t)(gi >> 1);
    const uint32_t vrb = smem_u32(sV + vrow * 512);

    float o[32][4];
    #pragma unroll
    for (int nt = 0; nt < 32; nt++) { o[nt][0] = o[nt][1] = o[nt][2] = o[nt][3] = 0.0f; }
    float m0 = -1e30f, m1 = -1e30f, l0 = 0.0f, l1 = 0.0f;

    for (int it = 0; it < NTOK / BN; it++) {
        // ---- QK: S[16 x 64] per warp. hi*hi fp32 acc; lo*hi fp16 acc.
        float sc[8][4];
        uint32_t cacc[8][2];
        #pragma unroll
        for (int j = 0; j < 8; j++) {
            sc[j][0] = sc[j][1] = sc[j][2] = sc[j][3] = 0.0f;
            cacc[j][0] = cacc[j][1] = 0u;
        }

        #pragma unroll 4
        for (int kc = 0; kc < 16; kc++) {
            const uint32_t offA = (((2 * kc + aS0) ^ aSw) << 4);
            uint32_t ah0, ah1, ah2, ah3, al0, al1, al2, al3;
            ldsm4(ah0, ah1, ah2, ah3, aHrb + offA);
            ldsm4(al0, al1, al2, al3, aLrb + offA);
            const uint32_t offB = (((2 * kc + bS) ^ bSw) << 4);
            #pragma unroll
            for (int kk = 0; kk < 4; kk++) {
                uint32_t bh0, bh1, bh2, bh3;
                ldsm4(bh0, bh1, bh2, bh3, bHrb + kk * 8192 + offB);
                mma16816(sc[2 * kk + 0], ah0, ah1, ah2, ah3, bh0, bh1);
                mma16816(sc[2 * kk + 1], ah0, ah1, ah2, ah3, bh2, bh3);
                mma16816h(cacc[2 * kk + 0], al0, al1, al2, al3, bh0, bh1);
                mma16816h(cacc[2 * kk + 1], al0, al1, al2, al3, bh2, bh3);
            }
        }

        // fold fp16 correction into fp32 scores
        #pragma unroll
        for (int j = 0; j < 8; j++) {
            float2 c01 = __half22float2(*(__half2*)&cacc[j][0]);
            float2 c23 = __half22float2(*(__half2*)&cacc[j][1]);
            sc[j][0] += c01.x; sc[j][1] += c01.y;
            sc[j][2] += c23.x; sc[j][3] += c23.y;
        }

        CP_WAIT(0);           // V(it) complete
        __syncthreads();      // all warps done reading sK

        if (it + 1 < NTOK / BN) {
            load_tile64_sw(sKh, Kh + (size_t)(it + 1) * BN * CCH, t);
            CP_COMMIT();
        }

        // ---- online softmax: max reduce + lazy rescale
        float mx0 = -1e30f, mx1 = -1e30f;
        #pragma unroll
        for (int j = 0; j < 8; j++) {
            mx0 = fmaxf(mx0, fmaxf(sc[j][0], sc[j][1]));
            mx1 = fmaxf(mx1, fmaxf(sc[j][2], sc[j][3]));
        }
        mx0 = fmaxf(mx0, __shfl_xor_sync(0xffffffffu, mx0, 1));
        mx0 = fmaxf(mx0, __shfl_xor_sync(0xffffffffu, mx0, 2));
        mx1 = fmaxf(mx1, __shfl_xor_sync(0xffffffffu, mx1, 1));
        mx1 = fmaxf(mx1, __shfl_xor_sync(0xffffffffu, mx1, 2));
        const bool upd = (mx0 > m0) || (mx1 > m1);
        const float mn0 = fmaxf(m0, mx0), mn1 = fmaxf(m1, mx1);
        const float f0 = __expf(m0 - mn0), f1 = __expf(m1 - mn1);
        m0 = mn0; m1 = mn1;

        if (__any_sync(0xffffffffu, upd)) {
            #pragma unroll
            for (int nt = 0; nt < 32; nt++) {
                o[nt][0] *= f0; o[nt][1] *= f0;
                o[nt][2] *= f1; o[nt][3] *= f1;
            }
        }

        // ---- exp/pack interleaved with PV (per 16-key group)
        float s0 = 0.0f, s1 = 0.0f;
        #pragma unroll
        for (int kk = 0; kk < 4; kk++) {
            const int j0 = 2 * kk, j1 = 2 * kk + 1;
            float e00 = __expf(sc[j0][0] - mn0);
            float e01 = __expf(sc[j0][1] - mn0);
            float e10 = __expf(sc[j0][2] - mn1);
            float e11 = __expf(sc[j0][3] - mn1);
            float g00 = __expf(sc[j1][0] - mn0);
            float g01 = __expf(sc[j1][1] - mn0);
            float g10 = __expf(sc[j1][2] - mn1);
            float g11 = __expf(sc[j1][3] - mn1);
            s0 += (e00 + e01) + (g00 + g01);
            s1 += (e10 + e11) + (g10 + g11);
            const uint32_t p0 = h2pack(e00, e01);
            const uint32_t p1 = h2pack(e10, e11);
            const uint32_t p2 = h2pack(g00, g01);
            const uint32_t p3 = h2pack(g10, g11);
            #pragma unroll
            for (int q = 0; q < 16; q++) {
                const uint32_t offV = (((2 * q + vS) ^ vSw) << 4);
                uint32_t v0, v1, v2, v3;
                ldsm4t(v0, v1, v2, v3, vrb + kk * 8192 + offV);
                mma16816(o[2 * q + 0], p0, p1, p2, p3, v0, v1);
                mma16816(o[2 * q + 1], p0, p1, p2, p3, v2, v3);
            }
        }
        s0 += __shfl_xor_sync(0xffffffffu, s0, 1);
        s0 += __shfl_xor_sync(0xffffffffu, s0, 2);
        s1 += __shfl_xor_sync(0xffffffffu, s1, 1);
        s1 += __shfl_xor_sync(0xffffffffu, s1, 2);
        l0 = l0 * f0 + s0;
        l1 = l1 * f1 + s1;

        __syncthreads();      // all warps done reading sV
        if (it + 1 < NTOK / BN) {
            load_tile64_sw(sV, Vv + (size_t)(it + 1) * BN * CCH, t);
            CP_COMMIT();
            CP_WAIT(1);       // K(it+1) complete; V(it+1) may stay in flight
        }
        __syncthreads();
    }

    // ---- epilogue: O /= l, store hi/lo fp16 pair
    const float inv0 = 1.0f / l0, inv1 = 1.0f / l1;
    const int row0 = n0 + wr0 + (lane >> 2);
    const size_t base = ((size_t)b * NTOK + row0) * CCH + ((lane & 3) << 1);
    __half* __restrict__ Yh0 = g_y_hi + base;
    __half* __restrict__ Yl0 = g_y_lo + base;
    #pragma unroll
    for (int nt = 0; nt < 32; nt++) {
        float v0 = o[nt][0] * inv0, v1 = o[nt][1] * inv0;
        float v2 = o[nt][2] * inv1, v3 = o[nt][3] * inv1;
        __half h0 = __float2half(v0), h1 = __float2half(v1);
        __half h2 = __float2half(v2), h3 = __float2half(v3);
        *(__half2*)(Yh0 + nt * 8)            = __halves2half2(h0, h1);
        *(__half2*)(Yh0 + nt * 8 + 8 * CCH)  = __halves2half2(h2, h3);
        *(__half2*)(Yl0 + nt * 8)            = __halves2half2(__float2half(v0 - __half2float(h0)),
                                                              __float2half(v1 - __half2float(h1)));
        *(__half2*)(Yl0 + nt * 8 + 8 * CCH)  = __halves2half2(__float2half(v2 - __half2float(h2)),
                                                              __float2half(v3 - __half2float(h3)));
    }
}

// =============================================================================
// out_tc: out[b,oc,n] = x + gamma * w_out @ Y   double-buffered k
// =============================================================================
#define OT_STG 40960

__device__ __forceinline__ void out_load_chunk(char* sb, const __half* Ah, const __half* Al,
                                               const __half* Bh, const __half* Bl,
                                               int m0, int n0, int k0, int t) {
    __half* sAh = (__half*)sb;
    __half* sAl = (__half*)(sb + 10240);
    __half* sBh = (__half*)(sb + 20480);
    __half* sBl = (__half*)(sb + 30720);
    const int r = t >> 1, hoff = (t & 1) * 16;
    cp16(smem_u32(sAh + r * PA_LD + hoff),     Ah + (m0 + r) * CCH + k0 + hoff);
    cp16(smem_u32(sAh + r * PA_LD + hoff + 8), Ah + (m0 + r) * CCH + k0 + hoff + 8);
    cp16(smem_u32(sAl + r * PA_LD + hoff),     Al + (m0 + r) * CCH + k0 + hoff);
    cp16(smem_u32(sAl + r * PA_LD + hoff + 8), Al + (m0 + r) * CCH + k0 + hoff + 8);
    cp16(smem_u32(sBh + r * PA_LD + hoff),     Bh + (size_t)(n0 + r) * CCH + k0 + hoff);
    cp16(smem_u32(sBh + r * PA_LD + hoff + 8), Bh + (size_t)(n0 + r) * CCH + k0 + hoff + 8);
    cp16(smem_u32(sBl + r * PA_LD + hoff),     Bl + (size_t)(n0 + r) * CCH + k0 + hoff);
    cp16(smem_u32(sBl + r * PA_LD + hoff + 8), Bl + (size_t)(n0 + r) * CCH + k0 + hoff + 8);
}

__global__ void __launch_bounds__(256) out_tc_kernel(const float* __restrict__ x,
                                                     const float* __restrict__ gamma,
                                                     float* __restrict__ out) {
    const int b  = blockIdx.z;
    const int n0 = blockIdx.x * 128;
    const int m0 = blockIdx.y * 128;

    const int t = threadIdx.x, lane = t & 31, warp = t >> 5;
    const int wr = warp & 3, wc = warp >> 2;

    const __half* __restrict__ Ah = g_w_hi + 3 * CCH * CCH;
    const __half* __restrict__ Al = g_w_lo + 3 * CCH * CCH;
    const __half* __restrict__ Bh = g_y_hi + (size_t)b * NTOK * CCH;
    const __half* __restrict__ Bl = g_y_lo + (size_t)b * NTOK * CCH;

    float acc[2][8][4] = {};
    const int gi = lane >> 3, li = lane & 7;
    const uint32_t aOff = (uint32_t)((wr * 32 + (lane & 15)) * PA_LD + ((lane >> 4) << 3)) * 2;
    const uint32_t bOff = (uint32_t)((wc * 64 + ((gi >> 1) << 3) + li) * PA_LD + ((gi & 1) << 3)) * 2;

    out_load_chunk(smem_raw, Ah, Al, Bh, Bl, m0, n0, 0, t);
    CP_COMMIT();

    for (int kc8 = 0; kc8 < 8; kc8++) {
        if (kc8 + 1 < 8) {
            out_load_chunk(smem_raw + ((kc8 + 1) & 1) * OT_STG, Ah, Al, Bh, Bl,
                           m0, n0, (kc8 + 1) * 32, t);
            CP_COMMIT();
            CP_WAIT(1);
        } else {
            CP_WAIT(0);
        }
        __syncthreads();

        char* sb = smem_raw + (kc8 & 1) * OT_STG;
        const uint32_t sAh32 = smem_u32(sb);
        const uint32_t sAl32 = smem_u32(sb + 10240);
        const uint32_t sBh32 = smem_u32(sb + 20480);
        const uint32_t sBl32 = smem_u32(sb + 30720);

        #pragma unroll
        for (int ks = 0; ks < 2; ks++) {
            const uint32_t ka = ks * 32;
            uint32_t ah[2][4], al[2][4];
            ldsm4(ah[0][0], ah[0][1], ah[0][2], ah[0][3], sAh32 + aOff + ka);
            ldsm4(ah[1][0], ah[1][1], ah[1][2], ah[1][3], sAh32 + aOff + ka + 16 * PA_LD * 2);
            ldsm4(al[0][0], al[0][1], al[0][2], al[0][3], sAl32 + aOff + ka);
            ldsm4(al[1][0], al[1][1], al[1][2], al[1][3], sAl32 + aOff + ka + 16 * PA_LD * 2);
            #pragma unroll
            for (int jn = 0; jn < 4; jn++) {
                uint32_t bhf[4], blf[4];
                ldsm4(bhf[0], bhf[1], bhf[2], bhf[3], sBh32 + bOff + ka + jn * 16 * PA_LD * 2);
                ldsm4(blf[0], blf[1], blf[2], blf[3], sBl32 + bOff + ka + jn * 16 * PA_LD * 2);
                #pragma unroll
                for (int mi = 0; mi < 2; mi++) {
                    mma16816(acc[mi][2 * jn + 0], ah[mi][0], ah[mi][1], ah[mi][2], ah[mi][3], bhf[0], bhf[1]);
                    mma16816(acc[mi][2 * jn + 1], ah[mi][0], ah[mi][1], ah[mi][2], ah[mi][3], bhf[2], bhf[3]);
                    mma16816(acc[mi][2 * jn + 0], ah[mi][0], ah[mi][1], ah[mi][2], ah[mi][3], blf[0], blf[1]);
                    mma16816(acc[mi][2 * jn + 1], ah[mi][0], ah[mi][1], ah[mi][2], ah[mi][3], blf[2], blf[3]);
                    mma16816(acc[mi][2 * jn + 0], al[mi][0], al[mi][1], al[mi][2], al[mi][3], bhf[0], bhf[1]);
                    mma16816(acc[mi][2 * jn + 1], al[mi][0], al[mi][1], al[mi][2], al[mi][3], bhf[2], bhf[3]);
                }
            }
        }
        __syncthreads();
    }

    const float gm = *gamma;
    const int mb = m0 + wr * 32 + (lane >> 2);
    const int nb = n0 + wc * 64 + (lane & 3) * 2;
    #pragma unroll
    for (int mi = 0; mi < 2; mi++)
        #pragma unroll
        for (int jn = 0; jn < 8; jn++) {
            const int m = mb + mi * 16, n = nb + jn * 8;
            {
                const size_t idx = ((size_t)b * CCH + m) * NTOK + n;
                float2 xv = *(const float2*)&x[idx];
                float2 r = {xv.x + gm * acc[mi][jn][0], xv.y + gm * acc[mi][jn][1]};
                *(float2*)&out[idx] = r;
            }
            {
                const size_t idx = ((size_t)b * CCH + m + 8) * NTOK + n;
                float2 xv = *(const float2*)&x[idx];
                float2 r = {xv.x + gm * acc[mi][jn][2], xv.y + gm * acc[mi][jn][3]};
                *(float2*)&out[idx] = r;
            }
        }
}

// =============================================================================
extern "C" void kernel_launch(void* const* d_in, const int* in_sizes, int n_in,
                              void* d_out, int out_size) {
    (void)in_sizes; (void)n_in; (void)out_size;
    const float* x      = (const float*)d_in[0];
    const float* w_th   = (const float*)d_in[1];
    const float* w_ph   = (const float*)d_in[2];
    const float* w_g    = (const float*)d_in[3];
    const float* w_out  = (const float*)d_in[4];
    const float* gamma  = (const float*)d_in[5];
    float* out = (float*)d_out;

    const int fsmem = 196864;          // Q hi/lo 128K + K hi 32K + V 32K (+pad)
    const int psmem = 2 * PJ_STG;
    const int osmem = 2 * OT_STG;
    cudaFuncSetAttribute(flash_kernel,   cudaFuncAttributeMaxDynamicSharedMemorySize, fsmem);
    cudaFuncSetAttribute(proj_tc_kernel, cudaFuncAttributeMaxDynamicSharedMemorySize, psmem);
    cudaFuncSetAttribute(out_tc_kernel,  cudaFuncAttributeMaxDynamicSharedMemorySize, osmem);

    split_all_kernel<<<4096 + 256, 256>>>(x, w_th, w_ph, w_g, w_out);
    proj_tc_kernel<<<dim3(NTOK / 128, CCH / 128, BSZ * 3), 256, psmem>>>();
    flash_kernel  <<<dim3(NTOK / BM, BSZ), 256, fsmem>>>();
    out_tc_kernel <<<dim3(NTOK / 128, CCH / 128, BSZ), 256, osmem>>>(x, gamma, out);
}

// round 15
// speedup vs baseline: 1.5306x; 1.2062x over previous
#include <cuda_runtime.h>
#include <cuda_fp16.h>
#include <cstdint>

#define BSZ  4
#define CCH  256
#define NTOK 4096

#define BM   128
#define BN   64

// ---------------- static device scratch (no allocation allowed) ----------------
__device__ __half g_th_hi[(size_t)BSZ * NTOK * CCH];
__device__ __half g_ph_hi[(size_t)BSZ * NTOK * CCH];
__device__ __half g_gv  [(size_t)BSZ * NTOK * CCH];
__device__ __half g_y_hi[(size_t)BSZ * NTOK * CCH];
__device__ __half g_y_lo[(size_t)BSZ * NTOK * CCH];
__device__ __half g_x_hi[(size_t)BSZ * CCH * NTOK];
__device__ __half g_x_lo[(size_t)BSZ * CCH * NTOK];
__device__ __half g_w_hi[4 * CCH * CCH];
__device__ __half g_w_lo[4 * CCH * CCH];

// ---------------- PTX helpers ----------------
__device__ __forceinline__ uint32_t smem_u32(const void* p) {
    return (uint32_t)__cvta_generic_to_shared(p);
}
__device__ __forceinline__ void cp16(uint32_t s, const void* g) {
    asm volatile("cp.async.cg.shared.global [%0], [%1], 16;\n" :: "r"(s), "l"(g));
}
#define CP_COMMIT() asm volatile("cp.async.commit_group;\n" ::: "memory")
#define CP_WAIT(n)  asm volatile("cp.async.wait_group %0;\n" :: "n"(n) : "memory")

__device__ __forceinline__ void ldsm4(uint32_t& r0, uint32_t& r1, uint32_t& r2, uint32_t& r3,
                                      uint32_t a) {
    asm volatile("ldmatrix.sync.aligned.m8n8.x4.shared.b16 {%0,%1,%2,%3}, [%4];\n"
                 : "=r"(r0), "=r"(r1), "=r"(r2), "=r"(r3) : "r"(a));
}
__device__ __forceinline__ void ldsm4t(uint32_t& r0, uint32_t& r1, uint32_t& r2, uint32_t& r3,
                                       uint32_t a) {
    asm volatile("ldmatrix.sync.aligned.m8n8.x4.trans.shared.b16 {%0,%1,%2,%3}, [%4];\n"
                 : "=r"(r0), "=r"(r1), "=r"(r2), "=r"(r3) : "r"(a));
}
__device__ __forceinline__ void mma16816(float* c, uint32_t a0, uint32_t a1, uint32_t a2,
                                         uint32_t a3, uint32_t b0, uint32_t b1) {
    asm volatile("mma.sync.aligned.m16n8k16.row.col.f32.f16.f16.f32 "
                 "{%0,%1,%2,%3}, {%4,%5,%6,%7}, {%8,%9}, {%0,%1,%2,%3};\n"
                 : "+f"(c[0]), "+f"(c[1]), "+f"(c[2]), "+f"(c[3])
                 : "r"(a0), "r"(a1), "r"(a2), "r"(a3), "r"(b0), "r"(b1));
}
__device__ __forceinline__ uint32_t h2pack(float a, float b) {
    __half2 h = __floats2half2_rn(a, b);
    return *reinterpret_cast<uint32_t*>(&h);
}

// ---- swizzled tile loaders: row stride 512B, 16B chunk c stored at (c ^ (row&7))
__device__ __forceinline__ void load_tile64_sw(char* dst, const __half* src, int t) {
    #pragma unroll
    for (int i = 0; i < 8; i++) {
        int idx = t + (i << 8);
        int r = idx >> 5, c = idx & 31;
        cp16(smem_u32(dst + r * 512 + ((c ^ (r & 7)) << 4)), src + (r << 8) + (c << 3));
    }
}
__device__ __forceinline__ void load_tile128_sw(char* dst, const __half* src, int t) {
    #pragma unroll
    for (int i = 0; i < 16; i++) {
        int idx = t + (i << 8);
        int r = idx >> 5, c = idx & 31;
        cp16(smem_u32(dst + r * 512 + ((c ^ (r & 7)) << 4)), src + (r << 8) + (c << 3));
    }
}

extern __shared__ char smem_raw[];

// =============================================================================
// Prep: split fp32 -> (hi, lo) fp16 pairs. One launch: x part + w part.
// =============================================================================
__global__ void split_all_kernel(const float* __restrict__ x,
                                 const float* __restrict__ w0, const float* __restrict__ w1,
                                 const float* __restrict__ w2, const float* __restrict__ w3) {
    const int blk = blockIdx.x;
    const float* __restrict__ src;
    __half *dhi, *dlo;
    int i;
    if (blk < 4096) {
        i = (blk * 256 + threadIdx.x) * 4;
        src = x; dhi = g_x_hi; dlo = g_x_lo;
    } else {
        const int wsel = (blk - 4096) >> 6;
        const int wblk = (blk - 4096) & 63;
        i = (wblk * 256 + threadIdx.x) * 4;
        src = (wsel == 0) ? w0 : (wsel == 1) ? w1 : (wsel == 2) ? w2 : w3;
        dhi = g_w_hi + wsel * CCH * CCH; dlo = g_w_lo + wsel * CCH * CCH;
    }
    float4 v = *(const float4*)&src[i];
    __half h0 = __float2half(v.x), h1 = __float2half(v.y);
    __half h2 = __float2half(v.z), h3 = __float2half(v.w);
    *(__half2*)&dhi[i]     = __halves2half2(h0, h1);
    *(__half2*)&dhi[i + 2] = __halves2half2(h2, h3);
    *(__half2*)&dlo[i]     = __halves2half2(__float2half(v.x - __half2float(h0)),
                                            __float2half(v.y - __half2float(h1)));
    *(__half2*)&dlo[i + 2] = __halves2half2(__float2half(v.z - __half2float(h2)),
                                            __float2half(v.w - __half2float(h3)));
}

// =============================================================================
// proj_tc: out[oc,n] = sum_c w[oc,c] * x[c,n]   split-fp16, double-buffered k
// All outputs single-pass fp16 (theta/phi hi, g).
// =============================================================================
#define PA_LD 40
#define PB_LD 136
#define PJ_STG 38912

__device__ __forceinline__ void proj_load_chunk(char* sb, const __half* Ah, const __half* Al,
                                                const __half* Bh, const __half* Bl,
                                                int m0, int n0, int k0, int t) {
    __half* sAh = (__half*)sb;
    __half* sAl = (__half*)(sb + 10240);
    __half* sBh = (__half*)(sb + 20480);
    __half* sBl = (__half*)(sb + 29184);
    {
        const int r = t >> 1, hoff = (t & 1) * 16;
        cp16(smem_u32(sAh + r * PA_LD + hoff),     Ah + (m0 + r) * CCH + k0 + hoff);
        cp16(smem_u32(sAh + r * PA_LD + hoff + 8), Ah + (m0 + r) * CCH + k0 + hoff + 8);
        cp16(smem_u32(sAl + r * PA_LD + hoff),     Al + (m0 + r) * CCH + k0 + hoff);
        cp16(smem_u32(sAl + r * PA_LD + hoff + 8), Al + (m0 + r) * CCH + k0 + hoff + 8);
    }
    {
        const int r = t >> 3, hoff = (t & 7) * 16;
        cp16(smem_u32(sBh + r * PB_LD + hoff),     Bh + (size_t)(k0 + r) * NTOK + n0 + hoff);
        cp16(smem_u32(sBh + r * PB_LD + hoff + 8), Bh + (size_t)(k0 + r) * NTOK + n0 + hoff + 8);
        cp16(smem_u32(sBl + r * PB_LD + hoff),     Bl + (size_t)(k0 + r) * NTOK + n0 + hoff);
        cp16(smem_u32(sBl + r * PB_LD + hoff + 8), Bl + (size_t)(k0 + r) * NTOK + n0 + hoff + 8);
    }
}

__global__ void __launch_bounds__(256) proj_tc_kernel() {
    const int b  = blockIdx.z / 3;
    const int w  = blockIdx.z % 3;
    const int n0 = blockIdx.x * 128;
    const int m0 = blockIdx.y * 128;

    const int t = threadIdx.x, lane = t & 31, warp = t >> 5;
    const int wr = warp & 3, wc = warp >> 2;

    const __half* __restrict__ Ah = g_w_hi + w * CCH * CCH;
    const __half* __restrict__ Al = g_w_lo + w * CCH * CCH;
    const __half* __restrict__ Bh = g_x_hi + (size_t)b * CCH * NTOK;
    const __half* __restrict__ Bl = g_x_lo + (size_t)b * CCH * NTOK;

    float acc[2][8][4] = {};
    const int gi = lane >> 3, li = lane & 7;
    const uint32_t aOff = (uint32_t)((wr * 32 + (lane & 15)) * PA_LD + ((lane >> 4) << 3)) * 2;
    const uint32_t bOff = (uint32_t)((((gi & 1) << 3) + li) * PB_LD + wc * 64 + ((gi >> 1) << 3)) * 2;

    proj_load_chunk(smem_raw, Ah, Al, Bh, Bl, m0, n0, 0, t);
    CP_COMMIT();

    for (int kc8 = 0; kc8 < 8; kc8++) {
        if (kc8 + 1 < 8) {
            proj_load_chunk(smem_raw + ((kc8 + 1) & 1) * PJ_STG, Ah, Al, Bh, Bl,
                            m0, n0, (kc8 + 1) * 32, t);
            CP_COMMIT();
            CP_WAIT(1);
        } else {
            CP_WAIT(0);
        }
        __syncthreads();

        char* sb = smem_raw + (kc8 & 1) * PJ_STG;
        const uint32_t sAh32 = smem_u32(sb);
        const uint32_t sAl32 = smem_u32(sb + 10240);
        const uint32_t sBh32 = smem_u32(sb + 20480);
        const uint32_t sBl32 = smem_u32(sb + 29184);

        #pragma unroll
        for (int ks = 0; ks < 2; ks++) {
            const uint32_t ka = ks * 32, kb = ks * 16 * PB_LD * 2;
            uint32_t ah[2][4], al[2][4];
            ldsm4(ah[0][0], ah[0][1], ah[0][2], ah[0][3], sAh32 + aOff + ka);
            ldsm4(ah[1][0], ah[1][1], ah[1][2], ah[1][3], sAh32 + aOff + ka + 16 * PA_LD * 2);
            ldsm4(al[0][0], al[0][1], al[0][2], al[0][3], sAl32 + aOff + ka);
            ldsm4(al[1][0], al[1][1], al[1][2], al[1][3], sAl32 + aOff + ka + 16 * PA_LD * 2);
            #pragma unroll
            for (int jn = 0; jn < 4; jn++) {
                uint32_t bhf[4], blf[4];
                ldsm4t(bhf[0], bhf[1], bhf[2], bhf[3], sBh32 + bOff + kb + jn * 32);
                ldsm4t(blf[0], blf[1], blf[2], blf[3], sBl32 + bOff + kb + jn * 32);
                #pragma unroll
                for (int mi = 0; mi < 2; mi++) {
                    mma16816(acc[mi][2 * jn + 0], ah[mi][0], ah[mi][1], ah[mi][2], ah[mi][3], bhf[0], bhf[1]);
                    mma16816(acc[mi][2 * jn + 1], ah[mi][0], ah[mi][1], ah[mi][2], ah[mi][3], bhf[2], bhf[3]);
                    mma16816(acc[mi][2 * jn + 0], ah[mi][0], ah[mi][1], ah[mi][2], ah[mi][3], blf[0], blf[1]);
                    mma16816(acc[mi][2 * jn + 1], ah[mi][0], ah[mi][1], ah[mi][2], ah[mi][3], blf[2], blf[3]);
                    mma16816(acc[mi][2 * jn + 0], al[mi][0], al[mi][1], al[mi][2], al[mi][3], bhf[0], bhf[1]);
                    mma16816(acc[mi][2 * jn + 1], al[mi][0], al[mi][1], al[mi][2], al[mi][3], bhf[2], bhf[3]);
                }
            }
        }
        __syncthreads();
    }

    __half* buf = (__half*)smem_raw;   // [128 n][136]
    const int mb = wr * 32 + (lane >> 2);
    const int nb = wc * 64 + (lane & 3) * 2;

    __syncthreads();
    #pragma unroll
    for (int mi = 0; mi < 2; mi++)
        #pragma unroll
        for (int jn = 0; jn < 8; jn++)
            #pragma unroll
            for (int e = 0; e < 4; e++) {
                const float v = acc[mi][jn][e];
                const int nl = nb + jn * 8 + (e & 1);
                const int ml = mb + mi * 16 + ((e >> 1) << 3);
                buf[nl * PB_LD + ml] = __float2half(v);
            }
    __syncthreads();
    __half* __restrict__ G = (w == 0) ? g_th_hi : (w == 1) ? g_ph_hi : g_gv;
    G += (size_t)b * NTOK * CCH;
    #pragma unroll
    for (int i = 0; i < 8; i++) {
        const int fi = t * 8 + i;
        const int row = fi >> 4, col8 = (fi & 15) * 8;
        *(float4*)&G[(size_t)(n0 + row) * CCH + m0 + col8] = *(float4*)&buf[row * PB_LD + col8];
    }
}

// =============================================================================
// flash attention, BM=128, BN=64. S = th_hi * ph_hi (pure fp16 in, fp32 acc).
// smem 128K: Qh 0 (64K) | Kh 64K (32K) | V 96K (32K)
// =============================================================================
__global__ void __launch_bounds__(256, 1) flash_kernel() {
    const int b  = blockIdx.y;
    const int n0 = blockIdx.x * BM;

    char* sQh = smem_raw;
    char* sKh = smem_raw + 65536;
    char* sV  = smem_raw + 98304;

    const int t    = threadIdx.x;
    const int lane = t & 31;
    const int warp = t >> 5;
    const int wr0  = warp * 16;

    const __half* __restrict__ Qh = g_th_hi + ((size_t)b * NTOK + n0) * CCH;
    const __half* __restrict__ Kh = g_ph_hi + (size_t)b * NTOK * CCH;
    const __half* __restrict__ Vv = g_gv    + (size_t)b * NTOK * CCH;

    load_tile128_sw(sQh, Qh, t);
    load_tile64_sw(sKh, Kh, t);
    load_tile64_sw(sV,  Vv, t);
    CP_COMMIT();
    CP_WAIT(0);
    __syncthreads();

    const int gi = lane >> 3, li = lane & 7;
    const int arow = wr0 + (lane & 15);
    const uint32_t aSw = (uint32_t)(arow & 7);
    const uint32_t aS0 = (uint32_t)(lane >> 4);
    const uint32_t aHrb = smem_u32(sQh + arow * 512);

    const int brow = ((gi >> 1) << 3) + li;
    const uint32_t bSw = (uint32_t)(brow & 7);
    const uint32_t bS  = (uint32_t)(gi & 1);
    const uint32_t bHrb = smem_u32(sKh + brow * 512);

    const int vrow = ((gi & 1) << 3) + li;
    const uint32_t vSw = (uint32_t)(vrow & 7);
    const uint32_t vS  = (uint32_t)(gi >> 1);
    const uint32_t vrb = smem_u32(sV + vrow * 512);

    float o[32][4];
    #pragma unroll
    for (int nt = 0; nt < 32; nt++) { o[nt][0] = o[nt][1] = o[nt][2] = o[nt][3] = 0.0f; }
    float m0 = -1e30f, m1 = -1e30f, l0 = 0.0f, l1 = 0.0f;

    for (int it = 0; it < NTOK / BN; it++) {
        // ---- QK: S[16 x 64] per warp, fp32 acc
        float sc[8][4];
        #pragma unroll
        for (int j = 0; j < 8; j++) sc[j][0] = sc[j][1] = sc[j][2] = sc[j][3] = 0.0f;

        #pragma unroll 4
        for (int kc = 0; kc < 16; kc++) {
            const uint32_t offA = (((2 * kc + aS0) ^ aSw) << 4);
            uint32_t ah0, ah1, ah2, ah3;
            ldsm4(ah0, ah1, ah2, ah3, aHrb + offA);
            const uint32_t offB = (((2 * kc + bS) ^ bSw) << 4);
            #pragma unroll
            for (int kk = 0; kk < 4; kk++) {
                uint32_t bh0, bh1, bh2, bh3;
                ldsm4(bh0, bh1, bh2, bh3, bHrb + kk * 8192 + offB);
                mma16816(sc[2 * kk + 0], ah0, ah1, ah2, ah3, bh0, bh1);
                mma16816(sc[2 * kk + 1], ah0, ah1, ah2, ah3, bh2, bh3);
            }
        }

        CP_WAIT(0);           // V(it) complete
        __syncthreads();      // all warps done reading sK

        if (it + 1 < NTOK / BN) {
            load_tile64_sw(sKh, Kh + (size_t)(it + 1) * BN * CCH, t);
            CP_COMMIT();
        }

        // ---- online softmax: max reduce + lazy rescale
        float mx0 = -1e30f, mx1 = -1e30f;
        #pragma unroll
        for (int j = 0; j < 8; j++) {
            mx0 = fmaxf(mx0, fmaxf(sc[j][0], sc[j][1]));
            mx1 = fmaxf(mx1, fmaxf(sc[j][2], sc[j][3]));
        }
        mx0 = fmaxf(mx0, __shfl_xor_sync(0xffffffffu, mx0, 1));
        mx0 = fmaxf(mx0, __shfl_xor_sync(0xffffffffu, mx0, 2));
        mx1 = fmaxf(mx1, __shfl_xor_sync(0xffffffffu, mx1, 1));
        mx1 = fmaxf(mx1, __shfl_xor_sync(0xffffffffu, mx1, 2));
        const bool upd = (mx0 > m0) || (mx1 > m1);
        const float mn0 = fmaxf(m0, mx0), mn1 = fmaxf(m1, mx1);
        const float f0 = __expf(m0 - mn0), f1 = __expf(m1 - mn1);
        m0 = mn0; m1 = mn1;

        if (__any_sync(0xffffffffu, upd)) {
            #pragma unroll
            for (int nt = 0; nt < 32; nt++) {
                o[nt][0] *= f0; o[nt][1] *= f0;
                o[nt][2] *= f1; o[nt][3] *= f1;
            }
        }

        // ---- exp/pack interleaved with PV (per 16-key group)
        float s0 = 0.0f, s1 = 0.0f;
        #pragma unroll
        for (int kk = 0; kk < 4; kk++) {
            const int j0 = 2 * kk, j1 = 2 * kk + 1;
            float e00 = __expf(sc[j0][0] - mn0);
            float e01 = __expf(sc[j0][1] - mn0);
            float e10 = __expf(sc[j0][2] - mn1);
            float e11 = __expf(sc[j0][3] - mn1);
            float g00 = __expf(sc[j1][0] - mn0);
            float g01 = __expf(sc[j1][1] - mn0);
            float g10 = __expf(sc[j1][2] - mn1);
            float g11 = __expf(sc[j1][3] - mn1);
            s0 += (e00 + e01) + (g00 + g01);
            s1 += (e10 + e11) + (g10 + g11);
            const uint32_t p0 = h2pack(e00, e01);
            const uint32_t p1 = h2pack(e10, e11);
            const uint32_t p2 = h2pack(g00, g01);
            const uint32_t p3 = h2pack(g10, g11);
            #pragma unroll
            for (int q = 0; q < 16; q++) {
                const uint32_t offV = (((2 * q + vS) ^ vSw) << 4);
                uint32_t v0, v1, v2, v3;
                ldsm4t(v0, v1, v2, v3, vrb + kk * 8192 + offV);
                mma16816(o[2 * q + 0], p0, p1, p2, p3, v0, v1);
                mma16816(o[2 * q + 1], p0, p1, p2, p3, v2, v3);
            }
        }
        s0 += __shfl_xor_sync(0xffffffffu, s0, 1);
        s0 += __shfl_xor_sync(0xffffffffu, s0, 2);
        s1 += __shfl_xor_sync(0xffffffffu, s1, 1);
        s1 += __shfl_xor_sync(0xffffffffu, s1, 2);
        l0 = l0 * f0 + s0;
        l1 = l1 * f1 + s1;

        __syncthreads();      // all warps done reading sV
        if (it + 1 < NTOK / BN) {
            load_tile64_sw(sV, Vv + (size_t)(it + 1) * BN * CCH, t);
            CP_COMMIT();
            CP_WAIT(1);       // K(it+1) complete; V(it+1) may stay in flight
        }
        __syncthreads();
    }

    // ---- epilogue: O /= l, store hi/lo fp16 pair
    const float inv0 = 1.0f / l0, inv1 = 1.0f / l1;
    const int row0 = n0 + wr0 + (lane >> 2);
    const size_t base = ((size_t)b * NTOK + row0) * CCH + ((lane & 3) << 1);
    __half* __restrict__ Yh0 = g_y_hi + base;
    __half* __restrict__ Yl0 = g_y_lo + base;
    #pragma unroll
    for (int nt = 0; nt < 32; nt++) {
        float v0 = o[nt][0] * inv0, v1 = o[nt][1] * inv0;
        float v2 = o[nt][2] * inv1, v3 = o[nt][3] * inv1;
        __half h0 = __float2half(v0), h1 = __float2half(v1);
        __half h2 = __float2half(v2), h3 = __float2half(v3);
        *(__half2*)(Yh0 + nt * 8)            = __halves2half2(h0, h1);
        *(__half2*)(Yh0 + nt * 8 + 8 * CCH)  = __halves2half2(h2, h3);
        *(__half2*)(Yl0 + nt * 8)            = __halves2half2(__float2half(v0 - __half2float(h0)),
                                                              __float2half(v1 - __half2float(h1)));
        *(__half2*)(Yl0 + nt * 8 + 8 * CCH)  = __halves2half2(__float2half(v2 - __half2float(h2)),
                                                              __float2half(v3 - __half2float(h3)));
    }
}

// =============================================================================
// out_tc: out[b,oc,n] = x + gamma * w_out @ Y   double-buffered k
// =============================================================================
#define OT_STG 40960

__device__ __forceinline__ void out_load_chunk(char* sb, const __half* Ah, const __half* Al,
                                               const __half* Bh, const __half* Bl,
                                               int m0, int n0, int k0, int t) {
    __half* sAh = (__half*)sb;
    __half* sAl = (__half*)(sb + 10240);
    __half* sBh = (__half*)(sb + 20480);
    __half* sBl = (__half*)(sb + 30720);
    const int r = t >> 1, hoff = (t & 1) * 16;
    cp16(smem_u32(sAh + r * PA_LD + hoff),     Ah + (m0 + r) * CCH + k0 + hoff);
    cp16(smem_u32(sAh + r * PA_LD + hoff + 8), Ah + (m0 + r) * CCH + k0 + hoff + 8);
    cp16(smem_u32(sAl + r * PA_LD + hoff),     Al + (m0 + r) * CCH + k0 + hoff);
    cp16(smem_u32(sAl + r * PA_LD + hoff + 8), Al + (m0 + r) * CCH + k0 + hoff + 8);
    cp16(smem_u32(sBh + r * PA_LD + hoff),     Bh + (size_t)(n0 + r) * CCH + k0 + hoff);
    cp16(smem_u32(sBh + r * PA_LD + hoff + 8), Bh + (size_t)(n0 + r) * CCH + k0 + hoff + 8);
    cp16(smem_u32(sBl + r * PA_LD + hoff),     Bl + (size_t)(n0 + r) * CCH + k0 + hoff);
    cp16(smem_u32(sBl + r * PA_LD + hoff + 8), Bl + (size_t)(n0 + r) * CCH + k0 + hoff + 8);
}

__global__ void __launch_bounds__(256) out_tc_kernel(const float* __restrict__ x,
                                                     const float* __restrict__ gamma,
                                                     float* __restrict__ out) {
    const int b  = blockIdx.z;
    const int n0 = blockIdx.x * 128;
    const int m0 = blockIdx.y * 128;

    const int t = threadIdx.x, lane = t & 31, warp = t >> 5;
    const int wr = warp & 3, wc = warp >> 2;

    const __half* __restrict__ Ah = g_w_hi + 3 * CCH * CCH;
    const __half* __restrict__ Al = g_w_lo + 3 * CCH * CCH;
    const __half* __restrict__ Bh = g_y_hi + (size_t)b * NTOK * CCH;
    const __half* __restrict__ Bl = g_y_lo + (size_t)b * NTOK * CCH;

    float acc[2][8][4] = {};
    const int gi = lane >> 3, li = lane & 7;
    const uint32_t aOff = (uint32_t)((wr * 32 + (lane & 15)) * PA_LD + ((lane >> 4) << 3)) * 2;
    const uint32_t bOff = (uint32_t)((wc * 64 + ((gi >> 1) << 3) + li) * PA_LD + ((gi & 1) << 3)) * 2;

    out_load_chunk(smem_raw, Ah, Al, Bh, Bl, m0, n0, 0, t);
    CP_COMMIT();

    for (int kc8 = 0; kc8 < 8; kc8++) {
        if (kc8 + 1 < 8) {
            out_load_chunk(smem_raw + ((kc8 + 1) & 1) * OT_STG, Ah, Al, Bh, Bl,
                           m0, n0, (kc8 + 1) * 32, t);
            CP_COMMIT();
            CP_WAIT(1);
        } else {
            CP_WAIT(0);
        }
        __syncthreads();

        char* sb = smem_raw + (kc8 & 1) * OT_STG;
        const uint32_t sAh32 = smem_u32(sb);
        const uint32_t sAl32 = smem_u32(sb + 10240);
        const uint32_t sBh32 = smem_u32(sb + 20480);
        const uint32_t sBl32 = smem_u32(sb + 30720);

        #pragma unroll
        for (int ks = 0; ks < 2; ks++) {
            const uint32_t ka = ks * 32;
            uint32_t ah[2][4], al[2][4];
            ldsm4(ah[0][0], ah[0][1], ah[0][2], ah[0][3], sAh32 + aOff + ka);
            ldsm4(ah[1][0], ah[1][1], ah[1][2], ah[1][3], sAh32 + aOff + ka + 16 * PA_LD * 2);
            ldsm4(al[0][0], al[0][1], al[0][2], al[0][3], sAl32 + aOff + ka);
            ldsm4(al[1][0], al[1][1], al[1][2], al[1][3], sAl32 + aOff + ka + 16 * PA_LD * 2);
            #pragma unroll
            for (int jn = 0; jn < 4; jn++) {
                uint32_t bhf[4], blf[4];
                ldsm4(bhf[0], bhf[1], bhf[2], bhf[3], sBh32 + bOff + ka + jn * 16 * PA_LD * 2);
                ldsm4(blf[0], blf[1], blf[2], blf[3], sBl32 + bOff + ka + jn * 16 * PA_LD * 2);
                #pragma unroll
                for (int mi = 0; mi < 2; mi++) {
                    mma16816(acc[mi][2 * jn + 0], ah[mi][0], ah[mi][1], ah[mi][2], ah[mi][3], bhf[0], bhf[1]);
                    mma16816(acc[mi][2 * jn + 1], ah[mi][0], ah[mi][1], ah[mi][2], ah[mi][3], bhf[2], bhf[3]);
                    mma16816(acc[mi][2 * jn + 0], ah[mi][0], ah[mi][1], ah[mi][2], ah[mi][3], blf[0], blf[1]);
                    mma16816(acc[mi][2 * jn + 1], ah[mi][0], ah[mi][1], ah[mi][2], ah[mi][3], blf[2], blf[3]);
                    mma16816(acc[mi][2 * jn + 0], al[mi][0], al[mi][1], al[mi][2], al[mi][3], bhf[0], bhf[1]);
                    mma16816(acc[mi][2 * jn + 1], al[mi][0], al[mi][1], al[mi][2], al[mi][3], bhf[2], bhf[3]);
                }
            }
        }
        __syncthreads();
    }

    const float gm = *gamma;
    const int mb = m0 + wr * 32 + (lane >> 2);
    const int nb = n0 + wc * 64 + (lane & 3) * 2;
    #pragma unroll
    for (int mi = 0; mi < 2; mi++)
        #pragma unroll
        for (int jn = 0; jn < 8; jn++) {
            const int m = mb + mi * 16, n = nb + jn * 8;
            {
                const size_t idx = ((size_t)b * CCH + m) * NTOK + n;
                float2 xv = *(const float2*)&x[idx];
                float2 r = {xv.x + gm * acc[mi][jn][0], xv.y + gm * acc[mi][jn][1]};
                *(float2*)&out[idx] = r;
            }
            {
                const size_t idx = ((size_t)b * CCH + m + 8) * NTOK + n;
                float2 xv = *(const float2*)&x[idx];
                float2 r = {xv.x + gm * acc[mi][jn][2], xv.y + gm * acc[mi][jn][3]};
                *(float2*)&out[idx] = r;
            }
        }
}

// =============================================================================
extern "C" void kernel_launch(void* const* d_in, const int* in_sizes, int n_in,
                              void* d_out, int out_size) {
    (void)in_sizes; (void)n_in; (void)out_size;
    const float* x      = (const float*)d_in[0];
    const float* w_th   = (const float*)d_in[1];
    const float* w_ph   = (const float*)d_in[2];
    const float* w_g    = (const float*)d_in[3];
    const float* w_out  = (const float*)d_in[4];
    const float* gamma  = (const float*)d_in[5];
    float* out = (float*)d_out;

    const int fsmem = 131328;          // Qh 64K + Kh 32K + V 32K (+pad)
    const int psmem = 2 * PJ_STG;
    const int osmem = 2 * OT_STG;
    cudaFuncSetAttribute(flash_kernel,   cudaFuncAttributeMaxDynamicSharedMemorySize, fsmem);
    cudaFuncSetAttribute(proj_tc_kernel, cudaFuncAttributeMaxDynamicSharedMemorySize, psmem);
    cudaFuncSetAttribute(out_tc_kernel,  cudaFuncAttributeMaxDynamicSharedMemorySize, osmem);

    split_all_kernel<<<4096 + 256, 256>>>(x, w_th, w_ph, w_g, w_out);
    proj_tc_kernel<<<dim3(NTOK / 128, CCH / 128, BSZ * 3), 256, psmem>>>();
    flash_kernel  <<<dim3(NTOK / BM, BSZ), 256, fsmem>>>();
    out_tc_kernel <<<dim3(NTOK / 128, CCH / 128, BSZ), 256, osmem>>>(x, gamma, out);
}

// round 17
// speedup vs baseline: 1.5423x; 1.0077x over previous
#include <cuda_runtime.h>
#include <cuda_fp16.h>
#include <cstdint>

#define BSZ  4
#define CCH  256
#define NTOK 4096

#define BM   128
#define BN   64

// ---------------- static device scratch (no allocation allowed) ----------------
__device__ __half g_th_hi[(size_t)BSZ * NTOK * CCH];
__device__ __half g_ph_hi[(size_t)BSZ * NTOK * CCH];
__device__ __half g_gv  [(size_t)BSZ * NTOK * CCH];
__device__ __half g_y_hi[(size_t)BSZ * NTOK * CCH];
__device__ __half g_y_lo[(size_t)BSZ * NTOK * CCH];
__device__ __half g_x_hi[(size_t)BSZ * CCH * NTOK];
__device__ __half g_x_lo[(size_t)BSZ * CCH * NTOK];
__device__ __half g_w_hi[4 * CCH * CCH];
__device__ __half g_w_lo[4 * CCH * CCH];

// ---------------- PTX helpers ----------------
__device__ __forceinline__ uint32_t smem_u32(const void* p) {
    return (uint32_t)__cvta_generic_to_shared(p);
}
__device__ __forceinline__ void cp16(uint32_t s, const void* g) {
    asm volatile("cp.async.cg.shared.global [%0], [%1], 16;\n" :: "r"(s), "l"(g));
}
#define CP_COMMIT() asm volatile("cp.async.commit_group;\n" ::: "memory")
#define CP_WAIT(n)  asm volatile("cp.async.wait_group %0;\n" :: "n"(n) : "memory")

__device__ __forceinline__ void ldsm4(uint32_t& r0, uint32_t& r1, uint32_t& r2, uint32_t& r3,
                                      uint32_t a) {
    asm volatile("ldmatrix.sync.aligned.m8n8.x4.shared.b16 {%0,%1,%2,%3}, [%4];\n"
                 : "=r"(r0), "=r"(r1), "=r"(r2), "=r"(r3) : "r"(a));
}
__device__ __forceinline__ void ldsm4t(uint32_t& r0, uint32_t& r1, uint32_t& r2, uint32_t& r3,
                                       uint32_t a) {
    asm volatile("ldmatrix.sync.aligned.m8n8.x4.trans.shared.b16 {%0,%1,%2,%3}, [%4];\n"
                 : "=r"(r0), "=r"(r1), "=r"(r2), "=r"(r3) : "r"(a));
}
__device__ __forceinline__ void mma16816(float* c, uint32_t a0, uint32_t a1, uint32_t a2,
                                         uint32_t a3, uint32_t b0, uint32_t b1) {
    asm volatile("mma.sync.aligned.m16n8k16.row.col.f32.f16.f16.f32 "
                 "{%0,%1,%2,%3}, {%4,%5,%6,%7}, {%8,%9}, {%0,%1,%2,%3};\n"
                 : "+f"(c[0]), "+f"(c[1]), "+f"(c[2]), "+f"(c[3])
                 : "r"(a0), "r"(a1), "r"(a2), "r"(a3), "r"(b0), "r"(b1));
}
__device__ __forceinline__ uint32_t h2pack(float a, float b) {
    __half2 h = __floats2half2_rn(a, b);
    return *reinterpret_cast<uint32_t*>(&h);
}

// ---- swizzled tile loaders: row stride 512B, 16B chunk c stored at (c ^ (row&7))
__device__ __forceinline__ void load_tile64_sw(char* dst, const __half* src, int t) {
    #pragma unroll
    for (int i = 0; i < 8; i++) {
        int idx = t + (i << 8);
        int r = idx >> 5, c = idx & 31;
        cp16(smem_u32(dst + r * 512 + ((c ^ (r & 7)) << 4)), src + (r << 8) + (c << 3));
    }
}
__device__ __forceinline__ void load_tile128_sw(char* dst, const __half* src, int t) {
    #pragma unroll
    for (int i = 0; i < 16; i++) {
        int idx = t + (i << 8);
        int r = idx >> 5, c = idx & 31;
        cp16(smem_u32(dst + r * 512 + ((c ^ (r & 7)) << 4)), src + (r << 8) + (c << 3));
    }
}

extern __shared__ char smem_raw[];

// =============================================================================
// Prep: split fp32 -> (hi, lo) fp16 pairs. One launch: x part + w part.
// =============================================================================
__global__ void split_all_kernel(const float* __restrict__ x,
                                 const float* __restrict__ w0, const float* __restrict__ w1,
                                 const float* __restrict__ w2, const float* __restrict__ w3) {
    const int blk = blockIdx.x;
    const float* __restrict__ src;
    __half *dhi, *dlo;
    int i;
    if (blk < 4096) {
        i = (blk * 256 + threadIdx.x) * 4;
        src = x; dhi = g_x_hi; dlo = g_x_lo;
    } else {
        const int wsel = (blk - 4096) >> 6;
        const int wblk = (blk - 4096) & 63;
        i = (wblk * 256 + threadIdx.x) * 4;
        src = (wsel == 0) ? w0 : (wsel == 1) ? w1 : (wsel == 2) ? w2 : w3;
        dhi = g_w_hi + wsel * CCH * CCH; dlo = g_w_lo + wsel * CCH * CCH;
    }
    float4 v = *(const float4*)&src[i];
    __half h0 = __float2half(v.x), h1 = __float2half(v.y);
    __half h2 = __float2half(v.z), h3 = __float2half(v.w);
    *(__half2*)&dhi[i]     = __halves2half2(h0, h1);
    *(__half2*)&dhi[i + 2] = __halves2half2(h2, h3);
    *(__half2*)&dlo[i]     = __halves2half2(__float2half(v.x - __half2float(h0)),
                                            __float2half(v.y - __half2float(h1)));
    *(__half2*)&dlo[i + 2] = __halves2half2(__float2half(v.z - __half2float(h2)),
                                            __float2half(v.w - __half2float(h3)));
}

// =============================================================================
// proj_tc: out[oc,n] = sum_c w[oc,c] * x[c,n]   split-fp16, double-buffered k
// All outputs single-pass fp16 (theta/phi hi, g).
// =============================================================================
#define PA_LD 40
#define PB_LD 136
#define PJ_STG 38912

__device__ __forceinline__ void proj_load_chunk(char* sb, const __half* Ah, const __half* Al,
                                                const __half* Bh, const __half* Bl,
                                                int m0, int n0, int k0, int t) {
    __half* sAh = (__half*)sb;
    __half* sAl = (__half*)(sb + 10240);
    __half* sBh = (__half*)(sb + 20480);
    __half* sBl = (__half*)(sb + 29184);
    {
        const int r = t >> 1, hoff = (t & 1) * 16;
        cp16(smem_u32(sAh + r * PA_LD + hoff),     Ah + (m0 + r) * CCH + k0 + hoff);
        cp16(smem_u32(sAh + r * PA_LD + hoff + 8), Ah + (m0 + r) * CCH + k0 + hoff + 8);
        cp16(smem_u32(sAl + r * PA_LD + hoff),     Al + (m0 + r) * CCH + k0 + hoff);
        cp16(smem_u32(sAl + r * PA_LD + hoff + 8), Al + (m0 + r) * CCH + k0 + hoff + 8);
    }
    {
        const int r = t >> 3, hoff = (t & 7) * 16;
        cp16(smem_u32(sBh + r * PB_LD + hoff),     Bh + (size_t)(k0 + r) * NTOK + n0 + hoff);
        cp16(smem_u32(sBh + r * PB_LD + hoff + 8), Bh + (size_t)(k0 + r) * NTOK + n0 + hoff + 8);
        cp16(smem_u32(sBl + r * PB_LD + hoff),     Bl + (size_t)(k0 + r) * NTOK + n0 + hoff);
        cp16(smem_u32(sBl + r * PB_LD + hoff + 8), Bl + (size_t)(k0 + r) * NTOK + n0 + hoff + 8);
    }
}

__global__ void __launch_bounds__(256) proj_tc_kernel() {
    const int b  = blockIdx.z / 3;
    const int w  = blockIdx.z % 3;
    const int n0 = blockIdx.x * 128;
    const int m0 = blockIdx.y * 128;

    const int t = threadIdx.x, lane = t & 31, warp = t >> 5;
    const int wr = warp & 3, wc = warp >> 2;

    const __half* __restrict__ Ah = g_w_hi + w * CCH * CCH;
    const __half* __restrict__ Al = g_w_lo + w * CCH * CCH;
    const __half* __restrict__ Bh = g_x_hi + (size_t)b * CCH * NTOK;
    const __half* __restrict__ Bl = g_x_lo + (size_t)b * CCH * NTOK;

    float acc[2][8][4] = {};
    const int gi = lane >> 3, li = lane & 7;
    const uint32_t aOff = (uint32_t)((wr * 32 + (lane & 15)) * PA_LD + ((lane >> 4) << 3)) * 2;
    const uint32_t bOff = (uint32_t)((((gi & 1) << 3) + li) * PB_LD + wc * 64 + ((gi >> 1) << 3)) * 2;

    proj_load_chunk(smem_raw, Ah, Al, Bh, Bl, m0, n0, 0, t);
    CP_COMMIT();

    for (int kc8 = 0; kc8 < 8; kc8++) {
        if (kc8 + 1 < 8) {
            proj_load_chunk(smem_raw + ((kc8 + 1) & 1) * PJ_STG, Ah, Al, Bh, Bl,
                            m0, n0, (kc8 + 1) * 32, t);
            CP_COMMIT();
            CP_WAIT(1);
        } else {
            CP_WAIT(0);
        }
        __syncthreads();

        char* sb = smem_raw + (kc8 & 1) * PJ_STG;
        const uint32_t sAh32 = smem_u32(sb);
        const uint32_t sAl32 = smem_u32(sb + 10240);
        const uint32_t sBh32 = smem_u32(sb + 20480);
        const uint32_t sBl32 = smem_u32(sb + 29184);

        #pragma unroll
        for (int ks = 0; ks < 2; ks++) {
            const uint32_t ka = ks * 32, kb = ks * 16 * PB_LD * 2;
            uint32_t ah[2][4], al[2][4];
            ldsm4(ah[0][0], ah[0][1], ah[0][2], ah[0][3], sAh32 + aOff + ka);
            ldsm4(ah[1][0], ah[1][1], ah[1][2], ah[1][3], sAh32 + aOff + ka + 16 * PA_LD * 2);
            ldsm4(al[0][0], al[0][1], al[0][2], al[0][3], sAl32 + aOff + ka);
            ldsm4(al[1][0], al[1][1], al[1][2], al[1][3], sAl32 + aOff + ka + 16 * PA_LD * 2);
            #pragma unroll
            for (int jn = 0; jn < 4; jn++) {
                uint32_t bhf[4], blf[4];
                ldsm4t(bhf[0], bhf[1], bhf[2], bhf[3], sBh32 + bOff + kb + jn * 32);
                ldsm4t(blf[0], blf[1], blf[2], blf[3], sBl32 + bOff + kb + jn * 32);
                #pragma unroll
                for (int mi = 0; mi < 2; mi++) {
                    mma16816(acc[mi][2 * jn + 0], ah[mi][0], ah[mi][1], ah[mi][2], ah[mi][3], bhf[0], bhf[1]);
                    mma16816(acc[mi][2 * jn + 1], ah[mi][0], ah[mi][1], ah[mi][2], ah[mi][3], bhf[2], bhf[3]);
                    mma16816(acc[mi][2 * jn + 0], ah[mi][0], ah[mi][1], ah[mi][2], ah[mi][3], blf[0], blf[1]);
                    mma16816(acc[mi][2 * jn + 1], ah[mi][0], ah[mi][1], ah[mi][2], ah[mi][3], blf[2], blf[3]);
                    mma16816(acc[mi][2 * jn + 0], al[mi][0], al[mi][1], al[mi][2], al[mi][3], bhf[0], bhf[1]);
                    mma16816(acc[mi][2 * jn + 1], al[mi][0], al[mi][1], al[mi][2], al[mi][3], bhf[2], bhf[3]);
                }
            }
        }
        __syncthreads();
    }

    __half* buf = (__half*)smem_raw;   // [128 n][136]
    const int mb = wr * 32 + (lane >> 2);
    const int nb = wc * 64 + (lane & 3) * 2;

    __syncthreads();
    #pragma unroll
    for (int mi = 0; mi < 2; mi++)
        #pragma unroll
        for (int jn = 0; jn < 8; jn++)
            #pragma unroll
            for (int e = 0; e < 4; e++) {
                const float v = acc[mi][jn][e];
                const int nl = nb + jn * 8 + (e & 1);
                const int ml = mb + mi * 16 + ((e >> 1) << 3);
                buf[nl * PB_LD + ml] = __float2half(v);
            }
    __syncthreads();
    __half* __restrict__ G = (w == 0) ? g_th_hi : (w == 1) ? g_ph_hi : g_gv;
    G += (size_t)b * NTOK * CCH;
    #pragma unroll
    for (int i = 0; i < 8; i++) {
        const int fi = t * 8 + i;
        const int row = fi >> 4, col8 = (fi & 15) * 8;
        *(float4*)&G[(size_t)(n0 + row) * CCH + m0 + col8] = *(float4*)&buf[row * PB_LD + col8];
    }
}

// =============================================================================
// flash attention, BM=128, BN=64. S = th_hi * ph_hi. K and V double-buffered,
// ONE sync + ONE wait per iteration.
// smem 192K: Qh 0 (64K) | K bufs 64K (2 x 32K) | V bufs 128K (2 x 32K)
// =============================================================================
__global__ void __launch_bounds__(256, 1) flash_kernel() {
    const int b  = blockIdx.y;
    const int n0 = blockIdx.x * BM;

    char* sQh = smem_raw;
    char* sKb = smem_raw + 65536;    // buffer stride 32768
    char* sVb = smem_raw + 131072;   // buffer stride 32768

    const int t    = threadIdx.x;
    const int lane = t & 31;
    const int warp = t >> 5;
    const int wr0  = warp * 16;

    const __half* __restrict__ Qh = g_th_hi + ((size_t)b * NTOK + n0) * CCH;
    const __half* __restrict__ Kh = g_ph_hi + (size_t)b * NTOK * CCH;
    const __half* __restrict__ Vv = g_gv    + (size_t)b * NTOK * CCH;

    // prologue: Q + tile 0
    load_tile128_sw(sQh, Qh, t);
    load_tile64_sw(sKb, Kh, t);
    load_tile64_sw(sVb, Vv, t);
    CP_COMMIT();

    const int gi = lane >> 3, li = lane & 7;
    const int arow = wr0 + (lane & 15);
    const uint32_t aSw = (uint32_t)(arow & 7);
    const uint32_t aS0 = (uint32_t)(lane >> 4);
    const uint32_t aHrb = smem_u32(sQh + arow * 512);

    const int brow = ((gi >> 1) << 3) + li;
    const uint32_t bSw = (uint32_t)(brow & 7);
    const uint32_t bS  = (uint32_t)(gi & 1);
    const uint32_t bHrb0 = smem_u32(sKb + brow * 512);

    const int vrow = ((gi & 1) << 3) + li;
    const uint32_t vSw = (uint32_t)(vrow & 7);
    const uint32_t vS  = (uint32_t)(gi >> 1);
    const uint32_t vrb0 = smem_u32(sVb + vrow * 512);

    float o[32][4];
    #pragma unroll
    for (int nt = 0; nt < 32; nt++) { o[nt][0] = o[nt][1] = o[nt][2] = o[nt][3] = 0.0f; }
    float m0 = -1e30f, m1 = -1e30f, l0 = 0.0f, l1 = 0.0f;

    for (int it = 0; it < NTOK / BN; it++) {
        CP_WAIT(0);           // tile it landed (issued one full iteration ago)
        __syncthreads();      // publish tile it; retire buffer consumed at it-1

        if (it + 1 < NTOK / BN) {   // prefetch it+1 into the freed buffer
            char* kb = sKb + ((it + 1) & 1) * 32768;
            char* vb = sVb + ((it + 1) & 1) * 32768;
            load_tile64_sw(kb, Kh + (size_t)(it + 1) * BN * CCH, t);
            load_tile64_sw(vb, Vv + (size_t)(it + 1) * BN * CCH, t);
            CP_COMMIT();
        }

        const uint32_t bHrb = bHrb0 + (uint32_t)(it & 1) * 32768;
        const uint32_t vrb  = vrb0  + (uint32_t)(it & 1) * 32768;

        // ---- QK: S[16 x 64] per warp, fp32 acc
        float sc[8][4];
        #pragma unroll
        for (int j = 0; j < 8; j++) sc[j][0] = sc[j][1] = sc[j][2] = sc[j][3] = 0.0f;

        #pragma unroll 4
        for (int kc = 0; kc < 16; kc++) {
            const uint32_t offA = (((2 * kc + aS0) ^ aSw) << 4);
            uint32_t ah0, ah1, ah2, ah3;
            ldsm4(ah0, ah1, ah2, ah3, aHrb + offA);
            const uint32_t offB = (((2 * kc + bS) ^ bSw) << 4);
            #pragma unroll
            for (int kk = 0; kk < 4; kk++) {
                uint32_t bh0, bh1, bh2, bh3;
                ldsm4(bh0, bh1, bh2, bh3, bHrb + kk * 8192 + offB);
                mma16816(sc[2 * kk + 0], ah0, ah1, ah2, ah3, bh0, bh1);
                mma16816(sc[2 * kk + 1], ah0, ah1, ah2, ah3, bh2, bh3);
            }
        }

        // ---- online softmax: max reduce + lazy rescale
        float mx0 = -1e30f, mx1 = -1e30f;
        #pragma unroll
        for (int j = 0; j < 8; j++) {
            mx0 = fmaxf(mx0, fmaxf(sc[j][0], sc[j][1]));
            mx1 = fmaxf(mx1, fmaxf(sc[j][2], sc[j][3]));
        }
        mx0 = fmaxf(mx0, __shfl_xor_sync(0xffffffffu, mx0, 1));
        mx0 = fmaxf(mx0, __shfl_xor_sync(0xffffffffu, mx0, 2));
        mx1 = fmaxf(mx1, __shfl_xor_sync(0xffffffffu, mx1, 1));
        mx1 = fmaxf(mx1, __shfl_xor_sync(0xffffffffu, mx1, 2));
        const bool upd = (mx0 > m0) || (mx1 > m1);
        const float mn0 = fmaxf(m0, mx0), mn1 = fmaxf(m1, mx1);
        const float f0 = __expf(m0 - mn0), f1 = __expf(m1 - mn1);
        m0 = mn0; m1 = mn1;

        if (__any_sync(0xffffffffu, upd)) {
            #pragma unroll
            for (int nt = 0; nt < 32; nt++) {
                o[nt][0] *= f0; o[nt][1] *= f0;
                o[nt][2] *= f1; o[nt][3] *= f1;
            }
        }

        // ---- exp/pack interleaved with PV (per 16-key group)
        float s0 = 0.0f, s1 = 0.0f;
        #pragma unroll
        for (int kk = 0; kk < 4; kk++) {
            const int j0 = 2 * kk, j1 = 2 * kk + 1;
            float e00 = __expf(sc[j0][0] - mn0);
            float e01 = __expf(sc[j0][1] - mn0);
            float e10 = __expf(sc[j0][2] - mn1);
            float e11 = __expf(sc[j0][3] - mn1);
            float g00 = __expf(sc[j1][0] - mn0);
            float g01 = __expf(sc[j1][1] - mn0);
            float g10 = __expf(sc[j1][2] - mn1);
            float g11 = __expf(sc[j1][3] - mn1);
            s0 += (e00 + e01) + (g00 + g01);
            s1 += (e10 + e11) + (g10 + g11);
            const uint32_t p0 = h2pack(e00, e01);
            const uint32_t p1 = h2pack(e10, e11);
            const uint32_t p2 = h2pack(g00, g01);
            const uint32_t p3 = h2pack(g10, g11);
            #pragma unroll
            for (int q = 0; q < 16; q++) {
                const uint32_t offV = (((2 * q + vS) ^ vSw) << 4);
                uint32_t v0, v1, v2, v3;
                ldsm4t(v0, v1, v2, v3, vrb + kk * 8192 + offV);
                mma16816(o[2 * q + 0], p0, p1, p2, p3, v0, v1);
                mma16816(o[2 * q + 1], p0, p1, p2, p3, v2, v3);
            }
        }
        s0 += __shfl_xor_sync(0xffffffffu, s0, 1);
        s0 += __shfl_xor_sync(0xffffffffu, s0, 2);
        s1 += __shfl_xor_sync(0xffffffffu, s1, 1);
        s1 += __shfl_xor_sync(0xffffffffu, s1, 2);
        l0 = l0 * f0 + s0;
        l1 = l1 * f1 + s1;
    }

    // ---- epilogue: O /= l, store hi/lo fp16 pair
    const float inv0 = 1.0f / l0, inv1 = 1.0f / l1;
    const int row0 = n0 + wr0 + (lane >> 2);
    const size_t base = ((size_t)b * NTOK + row0) * CCH + ((lane & 3) << 1);
    __half* __restrict__ Yh0 = g_y_hi + base;
    __half* __restrict__ Yl0 = g_y_lo + base;
    #pragma unroll
    for (int nt = 0; nt < 32; nt++) {
        float v0 = o[nt][0] * inv0, v1 = o[nt][1] * inv0;
        float v2 = o[nt][2] * inv1, v3 = o[nt][3] * inv1;
        __half h0 = __float2half(v0), h1 = __float2half(v1);
        __half h2 = __float2half(v2), h3 = __float2half(v3);
        *(__half2*)(Yh0 + nt * 8)            = __halves2half2(h0, h1);
        *(__half2*)(Yh0 + nt * 8 + 8 * CCH)  = __halves2half2(h2, h3);
        *(__half2*)(Yl0 + nt * 8)            = __halves2half2(__float2half(v0 - __half2float(h0)),
                                                              __float2half(v1 - __half2float(h1)));
        *(__half2*)(Yl0 + nt * 8 + 8 * CCH)  = __halves2half2(__float2half(v2 - __half2float(h2)),
                                                              __float2half(v3 - __half2float(h3)));
    }
}

// =============================================================================
// out_tc: out[b,oc,n] = x + gamma * w_out @ Y   double-buffered k
// =============================================================================
#define OT_STG 40960

__device__ __forceinline__ void out_load_chunk(char* sb, const __half* Ah, const __half* Al,
                                               const __half* Bh, const __half* Bl,
                                               int m0, int n0, int k0, int t) {
    __half* sAh = (__half*)sb;
    __half* sAl = (__half*)(sb + 10240);
    __half* sBh = (__half*)(sb + 20480);
    __half* sBl = (__half*)(sb + 30720);
    const int r = t >> 1, hoff = (t & 1) * 16;
    cp16(smem_u32(sAh + r * PA_LD + hoff),     Ah + (m0 + r) * CCH + k0 + hoff);
    cp16(smem_u32(sAh + r * PA_LD + hoff + 8), Ah + (m0 + r) * CCH + k0 + hoff + 8);
    cp16(smem_u32(sAl + r * PA_LD + hoff),     Al + (m0 + r) * CCH + k0 + hoff);
    cp16(smem_u32(sAl + r * PA_LD + hoff + 8), Al + (m0 + r) * CCH + k0 + hoff + 8);
    cp16(smem_u32(sBh + r * PA_LD + hoff),     Bh + (size_t)(n0 + r) * CCH + k0 + hoff);
    cp16(smem_u32(sBh + r * PA_LD + hoff + 8), Bh + (size_t)(n0 + r) * CCH + k0 + hoff + 8);
    cp16(smem_u32(sBl + r * PA_LD + hoff),     Bl + (size_t)(n0 + r) * CCH + k0 + hoff);
    cp16(smem_u32(sBl + r * PA_LD + hoff + 8), Bl + (size_t)(n0 + r) * CCH + k0 + hoff + 8);
}

__global__ void __launch_bounds__(256) out_tc_kernel(const float* __restrict__ x,
                                                     const float* __restrict__ gamma,
                                                     float* __restrict__ out) {
    const int b  = blockIdx.z;
    const int n0 = blockIdx.x * 128;
    const int m0 = blockIdx.y * 128;

    const int t = threadIdx.x, lane = t & 31, warp = t >> 5;
    const int wr = warp & 3, wc = warp >> 2;

    const __half* __restrict__ Ah = g_w_hi + 3 * CCH * CCH;
    const __half* __restrict__ Al = g_w_lo + 3 * CCH * CCH;
    const __half* __restrict__ Bh = g_y_hi + (size_t)b * NTOK * CCH;
    const __half* __restrict__ Bl = g_y_lo + (size_t)b * NTOK * CCH;

    float acc[2][8][4] = {};
    const int gi = lane >> 3, li = lane & 7;
    const uint32_t aOff = (uint32_t)((wr * 32 + (lane & 15)) * PA_LD + ((lane >> 4) << 3)) * 2;
    const uint32_t bOff = (uint32_t)((wc * 64 + ((gi >> 1) << 3) + li) * PA_LD + ((gi & 1) << 3)) * 2;

    out_load_chunk(smem_raw, Ah, Al, Bh, Bl, m0, n0, 0, t);
    CP_COMMIT();

    for (int kc8 = 0; kc8 < 8; kc8++) {
        if (kc8 + 1 < 8) {
            out_load_chunk(smem_raw + ((kc8 + 1) & 1) * OT_STG, Ah, Al, Bh, Bl,
                           m0, n0, (kc8 + 1) * 32, t);
            CP_COMMIT();
            CP_WAIT(1);
        } else {
            CP_WAIT(0);
        }
        __syncthreads();

        char* sb = smem_raw + (kc8 & 1) * OT_STG;
        const uint32_t sAh32 = smem_u32(sb);
        const uint32_t sAl32 = smem_u32(sb + 10240);
        const uint32_t sBh32 = smem_u32(sb + 20480);
        const uint32_t sBl32 = smem_u32(sb + 30720);

        #pragma unroll
        for (int ks = 0; ks < 2; ks++) {
            const uint32_t ka = ks * 32;
            uint32_t ah[2][4], al[2][4];
            ldsm4(ah[0][0], ah[0][1], ah[0][2], ah[0][3], sAh32 + aOff + ka);
            ldsm4(ah[1][0], ah[1][1], ah[1][2], ah[1][3], sAh32 + aOff + ka + 16 * PA_LD * 2);
            ldsm4(al[0][0], al[0][1], al[0][2], al[0][3], sAl32 + aOff + ka);
            ldsm4(al[1][0], al[1][1], al[1][2], al[1][3], sAl32 + aOff + ka + 16 * PA_LD * 2);
            #pragma unroll
            for (int jn = 0; jn < 4; jn++) {
                uint32_t bhf[4], blf[4];
                ldsm4(bhf[0], bhf[1], bhf[2], bhf[3], sBh32 + bOff + ka + jn * 16 * PA_LD * 2);
                ldsm4(blf[0], blf[1], blf[2], blf[3], sBl32 + bOff + ka + jn * 16 * PA_LD * 2);
                #pragma unroll
                for (int mi = 0; mi < 2; mi++) {
                    mma16816(acc[mi][2 * jn + 0], ah[mi][0], ah[mi][1], ah[mi][2], ah[mi][3], bhf[0], bhf[1]);
                    mma16816(acc[mi][2 * jn + 1], ah[mi][0], ah[mi][1], ah[mi][2], ah[mi][3], bhf[2], bhf[3]);
                    mma16816(acc[mi][2 * jn + 0], ah[mi][0], ah[mi][1], ah[mi][2], ah[mi][3], blf[0], blf[1]);
                    mma16816(acc[mi][2 * jn + 1], ah[mi][0], ah[mi][1], ah[mi][2], ah[mi][3], blf[2], blf[3]);
                    mma16816(acc[mi][2 * jn + 0], al[mi][0], al[mi][1], al[mi][2], al[mi][3], bhf[0], bhf[1]);
                    mma16816(acc[mi][2 * jn + 1], al[mi][0], al[mi][1], al[mi][2], al[mi][3], bhf[2], bhf[3]);
                }
            }
        }
        __syncthreads();
    }

    const float gm = *gamma;
    const int mb = m0 + wr * 32 + (lane >> 2);
    const int nb = n0 + wc * 64 + (lane & 3) * 2;
    #pragma unroll
    for (int mi = 0; mi < 2; mi++)
        #pragma unroll
        for (int jn = 0; jn < 8; jn++) {
            const int m = mb + mi * 16, n = nb + jn * 8;
            {
                const size_t idx = ((size_t)b * CCH + m) * NTOK + n;
                float2 xv = *(const float2*)&x[idx];
                float2 r = {xv.x + gm * acc[mi][jn][0], xv.y + gm * acc[mi][jn][1]};
                *(float2*)&out[idx] = r;
            }
            {
                const size_t idx = ((size_t)b * CCH + m + 8) * NTOK + n;
                float2 xv = *(const float2*)&x[idx];
                float2 r = {xv.x + gm * acc[mi][jn][2], xv.y + gm * acc[mi][jn][3]};
                *(float2*)&out[idx] = r;
            }
        }
}

// =============================================================================
extern "C" void kernel_launch(void* const* d_in, const int* in_sizes, int n_in,
                              void* d_out, int out_size) {
    (void)in_sizes; (void)n_in; (void)out_size;
    const float* x      = (const float*)d_in[0];
    const float* w_th   = (const float*)d_in[1];
    const float* w_ph   = (const float*)d_in[2];
    const float* w_g    = (const float*)d_in[3];
    const float* w_out  = (const float*)d_in[4];
    const float* gamma  = (const float*)d_in[5];
    float* out = (float*)d_out;

    const int fsmem = 197120;          // Qh 64K + K 2x32K + V 2x32K (+pad)
    const int psmem = 2 * PJ_STG;
    const int osmem = 2 * OT_STG;
    cudaFuncSetAttribute(flash_kernel,   cudaFuncAttributeMaxDynamicSharedMemorySize, fsmem);
    cudaFuncSetAttribute(proj_tc_kernel, cudaFuncAttributeMaxDynamicSharedMemorySize, psmem);
    cudaFuncSetAttribute(out_tc_kernel,  cudaFuncAttributeMaxDynamicSharedMemorySize, osmem);

    split_all_kernel<<<4096 + 256, 256>>>(x, w_th, w_ph, w_g, w_out);
    proj_tc_kernel<<<dim3(NTOK / 128, CCH / 128, BSZ * 3), 256, psmem>>>();
    flash_kernel  <<<dim3(NTOK / BM, BSZ), 256, fsmem>>>();
    out_tc_kernel <<<dim3(NTOK / 128, CCH / 128, BSZ), 256, osmem>>>(x, gamma, out);
}